// round 9
// baseline (speedup 1.0000x reference)
#include <cuda_runtime.h>
#include <cuda_bf16.h>

#define NN 50000
#define NE 800000
#define NG 128
#define DD 128
#define NL 4
#define NC 10
#define TM 64
#define NUM_TILES ((NN + TM - 1) / TM)   // 782

// ---------------- device scratch ----------------
__device__ float g_hbuf[2][NN * DD];
__device__ int   g_deg[NN];
__device__ int   g_rowptr[NN + 1];
__device__ int   g_cursor[NN];
__device__ int   g_colsrc[NE];
__device__ int   g_gstart[NG + 1];
__device__ int   g_nodeg[NN];
__device__ float g_countsf[NG];
__device__ float g_sum2[2][NG * DD];
__device__ float g_sumsq2[2][NG * DD];
__device__ float g_gsum[NG * DD];
__device__ int   g_blocksum[256];
__device__ int   g_blockpre[256];
__device__ int   g_ei64, g_b64;
__device__ unsigned g_sync_count = 0;
__device__ volatile unsigned g_sync_gen = 0;

// ---------------- helpers ----------------
__device__ __forceinline__ unsigned smem_u32(const void* p) {
    unsigned a;
    asm("{ .reg .u64 t; cvta.to.shared.u64 t, %1; cvt.u32.u64 %0, t; }" : "=r"(a) : "l"(p));
    return a;
}
// swizzled byte offset inside a [rows x 256 bytes] bf16 tile
__device__ __forceinline__ unsigned swb(int r, int kb) {
    unsigned w = (unsigned)kb & 127u;
    unsigned sw = w ^ (((unsigned)r & 7u) << 4);
    return (unsigned)r * 256u + ((unsigned)kb & 128u) + sw;
}
__device__ __forceinline__ unsigned pack_bf2(float a, float b) {
    __nv_bfloat162 p = __floats2bfloat162_rn(a, b);
    return *reinterpret_cast<unsigned*>(&p);
}
__device__ __forceinline__ float4 f4add(float4 a, float4 b) {
    a.x += b.x; a.y += b.y; a.z += b.z; a.w += b.w; return a;
}
__device__ __forceinline__ void ldsm4(unsigned* r, unsigned addr) {
    asm volatile("ldmatrix.sync.aligned.m8n8.x4.shared.b16 {%0,%1,%2,%3}, [%4];"
        : "=r"(r[0]), "=r"(r[1]), "=r"(r[2]), "=r"(r[3]) : "r"(addr));
}
__device__ __forceinline__ void mma16816(float* d, const unsigned* a, const unsigned* b) {
    asm volatile("mma.sync.aligned.m16n8k16.row.col.f32.bf16.bf16.f32 "
        "{%0,%1,%2,%3}, {%4,%5,%6,%7}, {%8,%9}, {%0,%1,%2,%3};"
        : "+f"(d[0]), "+f"(d[1]), "+f"(d[2]), "+f"(d[3])
        : "r"(a[0]), "r"(a[1]), "r"(a[2]), "r"(a[3]), "r"(b[0]), "r"(b[1]));
}
#define BAR_CONS() asm volatile("bar.sync 3, 128;" ::: "memory")

// ---------------- grid-wide barrier (all blocks resident) ----------------
__device__ __forceinline__ void gsync() {
    __syncthreads();
    if (threadIdx.x == 0) {
        unsigned gen = g_sync_gen;
        __threadfence();
        if (atomicAdd(&g_sync_count, 1u) == gridDim.x - 1) {
            g_sync_count = 0;
            __threadfence();
            g_sync_gen = gen + 1;
        } else {
            while (g_sync_gen == gen) { }
        }
        __threadfence();
    }
    __syncthreads();
}

// ---------------- fused persistent preprocessing ----------------
__global__ void __launch_bounds__(256) k_pre(const void* __restrict__ ei,
                                             const void* __restrict__ bat) {
    __shared__ int sscan[256];
    int tid = threadIdx.x, bid = blockIdx.x;
    int gtid = bid * 256 + tid, gsz = gridDim.x * 256;

    // phase 1: dtype detect (block 0, warp 0) + zero arrays
    if (bid == 0 && tid < 32) {
        const int* ei_w = (const int*)ei;
        const int* b_w = (const int*)bat;
        int ok1 = (ei_w[2 * tid + 1] == 0) && (ei_w[2 * (tid + 32) + 1] == 0);
        int a = __all_sync(0xffffffffu, ok1);
        int ok2 = (b_w[20001 + 2 * tid] == 0) && (b_w[20065 + 2 * tid] == 0);
        int b = __all_sync(0xffffffffu, ok2);
        if (tid == 0) { g_ei64 = a; g_b64 = b; }
    }
    for (int i = gtid; i < NN; i += gsz) g_deg[i] = 0;
    for (int i = gtid; i < NG * DD; i += gsz) {
        g_sum2[0][i] = 0.f; g_sum2[1][i] = 0.f;
        g_sumsq2[0][i] = 0.f; g_sumsq2[1][i] = 0.f;
        g_gsum[i] = 0.f;
    }
    gsync();

    // phase 2: graph bounds + degree histogram
    int e64 = g_ei64, b64 = g_b64;
    for (int i = gtid; i < NN; i += gsz) {
        int bi = b64 ? (int)((const long long*)bat)[i] : ((const int*)bat)[i];
        g_nodeg[i] = bi;
        int prev = -1;
        if (i > 0)
            prev = b64 ? (int)((const long long*)bat)[i - 1] : ((const int*)bat)[i - 1];
        for (int g = prev + 1; g <= bi; g++) g_gstart[g] = i;
        if (i == NN - 1)
            for (int g = bi + 1; g <= NG; g++) g_gstart[g] = NN;
    }
    for (int e = gtid; e < NE; e += gsz) {
        int d = e64 ? (int)((const long long*)ei)[NE + e] : ((const int*)ei)[NE + e];
        atomicAdd(&g_deg[d], 1);
    }
    gsync();

    // phase 3a: per-thread chunk sums + block scan
    const int CH = (NN + gsz - 1) / gsz;
    int base = gtid * CH;
    int s = 0;
    for (int j = 0; j < CH; j++) { int idx = base + j; if (idx < NN) s += g_deg[idx]; }
    sscan[tid] = s;
    __syncthreads();
    for (int off = 1; off < 256; off <<= 1) {
        int v = (tid >= off) ? sscan[tid - off] : 0;
        __syncthreads();
        sscan[tid] += v;
        __syncthreads();
    }
    int thr_excl = sscan[tid] - s;
    if (tid == 255) g_blocksum[bid] = sscan[255];
    gsync();

    // phase 3b: block 0 scans block totals (exclusive)
    if (bid == 0) {
        int v = (tid < (int)gridDim.x) ? g_blocksum[tid] : 0;
        sscan[tid] = v;
        __syncthreads();
        for (int off = 1; off < 256; off <<= 1) {
            int u = (tid >= off) ? sscan[tid - off] : 0;
            __syncthreads();
            sscan[tid] += u;
            __syncthreads();
        }
        if (tid < (int)gridDim.x) g_blockpre[tid] = sscan[tid] - v;
    }
    gsync();

    // phase 3c: write rowptr/cursor; counts
    int off = g_blockpre[bid] + thr_excl;
    for (int j = 0; j < CH; j++) {
        int idx = base + j;
        if (idx < NN) { g_rowptr[idx] = off; g_cursor[idx] = off; off += g_deg[idx]; }
    }
    if (gtid == 0) g_rowptr[NN] = NE;
    if (gtid < NG)
        g_countsf[gtid] = fmaxf((float)(g_gstart[gtid + 1] - g_gstart[gtid]), 1.f);
    gsync();

    // phase 4: fill CSR columns
    for (int e = gtid; e < NE; e += gsz) {
        int src, dst;
        if (e64) {
            src = (int)((const long long*)ei)[e];
            dst = (int)((const long long*)ei)[NE + e];
        } else {
            src = ((const int*)ei)[e];
            dst = ((const int*)ei)[NE + e];
        }
        g_colsrc[atomicAdd(&g_cursor[dst], 1)] = src;
    }
}

// ---------------- fused layer: pipelined gather || bf16x3 MMA ----------------
#define SM_B1H 0
#define SM_B1L 32768
#define SM_B2H 65536
#define SM_B2L 98304
#define SM_BI1 131072
#define SM_BI2 131584
#define SM_ABUF0 132096
#define SM_ABUF1 164864
#define SM_SCR  197632
#define DYN_SMEM (201728 + 1024)
// A buffer layout: hi at +0 (16KB), lo at +16384

__device__ __forceinline__ void gemm_x3_c(unsigned sbase, unsigned aH, unsigned aL,
                                          unsigned bH, unsigned bL,
                                          int m0, int lane, float acc[16][4]) {
    int aRow = lane & 15, aKoff = (lane >> 4) * 16;
    int bRow = (lane & 7) + (lane >> 4) * 8;
    int bHalf = ((lane >> 3) & 1) * 16;
#pragma unroll 1
    for (int ks = 0; ks < 8; ks++) {
        int kb = ks * 32;
        unsigned ah[4], al[4];
        ldsm4(ah, sbase + aH + swb(m0 + aRow, kb + aKoff));
        ldsm4(al, sbase + aL + swb(m0 + aRow, kb + aKoff));
#pragma unroll
        for (int np = 0; np < 8; np++) {
            unsigned bh[4], bl[4];
            ldsm4(bh, sbase + bH + swb(np * 16 + bRow, kb + bHalf));
            ldsm4(bl, sbase + bL + swb(np * 16 + bRow, kb + bHalf));
            mma16816(acc[np * 2], ah, bh);
            mma16816(acc[np * 2], al, bh);
            mma16816(acc[np * 2], ah, bl);
            mma16816(acc[np * 2 + 1], ah, bh + 2);
            mma16816(acc[np * 2 + 1], al, bh + 2);
            mma16816(acc[np * 2 + 1], ah, bl + 2);
        }
    }
}

__global__ void __launch_bounds__(256, 1) k_layer(
    const float* __restrict__ h_in, float* __restrict__ h_out,
    const float* __restrict__ W1, const float* __restrict__ B1,
    const float* __restrict__ W2, const float* __restrict__ B2,
    int layer)
{
    extern __shared__ char smraw[];
    char* sm = (char*)(((unsigned long long)smraw + 1023ull) & ~1023ull);
    unsigned sbase = smem_u32(sm);
    int tid = threadIdx.x, lane = tid & 31, wid = tid >> 5;
    int par = layer & 1;

    // stage W^T hi/lo (swizzled) + biases
    for (int idx = tid; idx < DD * DD; idx += 256) {
        int k = idx >> 7, n = idx & 127;
        float v1 = W1[idx], v2 = W2[idx];
        unsigned o = swb(n, 2 * k);
        __nv_bfloat16 h1 = __float2bfloat16(v1), h2 = __float2bfloat16(v2);
        *(__nv_bfloat16*)(sm + SM_B1H + o) = h1;
        *(__nv_bfloat16*)(sm + SM_B1L + o) = __float2bfloat16(v1 - __bfloat162float(h1));
        *(__nv_bfloat16*)(sm + SM_B2H + o) = h2;
        *(__nv_bfloat16*)(sm + SM_B2L + o) = __float2bfloat16(v2 - __bfloat162float(h2));
    }
    if (tid < 128) {
        ((float*)(sm + SM_BI1))[tid] = B1[tid];
        ((float*)(sm + SM_BI2))[tid] = B2[tid];
    }
    __syncthreads();

    const float4* hin4 = (const float4*)h_in;
    const float* bi1 = (const float*)(sm + SM_BI1);
    const float* bi2 = (const float*)(sm + SM_BI2);
    float* scrS = (float*)(sm + SM_SCR);
    float* scrQ = scrS + 512;

    const int G = gridDim.x;
    int tp = blockIdx.x;   // producer tile
    int tc = -1;           // consumer tile
    int pb = 0;            // producer buffer index

    for (;;) {
        bool prod_active = (tp < NUM_TILES);
        bool cons_active = (tc >= 0);
        if (!prod_active && !cons_active) break;

        if (wid < 4 && prod_active) {
            // ---- producer: gather 16 nodes, split hi/lo, STS swizzled ----
            unsigned aBuf = (pb ? SM_ABUF1 : SM_ABUF0);
#pragma unroll 1
            for (int mi = 0; mi < 16; mi++) {
                int m = wid * 16 + mi;
                int n = tp * TM + m;
                float4 t = make_float4(0.f, 0.f, 0.f, 0.f);
                if (n < NN) {
                    float4 a0 = t, a1 = t, a2 = t, a3 = t, a4 = t, a5 = t, a6 = t, a7 = t;
                    int beg = g_rowptr[n], end = g_rowptr[n + 1];
                    int e = beg;
                    for (; e + 8 <= end; e += 8) {
                        int s0 = g_colsrc[e],     s1 = g_colsrc[e + 1];
                        int s2 = g_colsrc[e + 2], s3 = g_colsrc[e + 3];
                        int s4 = g_colsrc[e + 4], s5 = g_colsrc[e + 5];
                        int s6 = g_colsrc[e + 6], s7 = g_colsrc[e + 7];
                        a0 = f4add(a0, __ldg(&hin4[s0 * 32 + lane]));
                        a1 = f4add(a1, __ldg(&hin4[s1 * 32 + lane]));
                        a2 = f4add(a2, __ldg(&hin4[s2 * 32 + lane]));
                        a3 = f4add(a3, __ldg(&hin4[s3 * 32 + lane]));
                        a4 = f4add(a4, __ldg(&hin4[s4 * 32 + lane]));
                        a5 = f4add(a5, __ldg(&hin4[s5 * 32 + lane]));
                        a6 = f4add(a6, __ldg(&hin4[s6 * 32 + lane]));
                        a7 = f4add(a7, __ldg(&hin4[s7 * 32 + lane]));
                    }
                    if (e + 4 <= end) {
                        int s0 = g_colsrc[e],     s1 = g_colsrc[e + 1];
                        int s2 = g_colsrc[e + 2], s3 = g_colsrc[e + 3];
                        a0 = f4add(a0, __ldg(&hin4[s0 * 32 + lane]));
                        a1 = f4add(a1, __ldg(&hin4[s1 * 32 + lane]));
                        a2 = f4add(a2, __ldg(&hin4[s2 * 32 + lane]));
                        a3 = f4add(a3, __ldg(&hin4[s3 * 32 + lane]));
                        e += 4;
                    }
                    for (; e < end; e++)
                        a0 = f4add(a0, __ldg(&hin4[g_colsrc[e] * 32 + lane]));
                    float4 s01 = f4add(f4add(a0, a1), f4add(a2, a3));
                    float4 s23 = f4add(f4add(a4, a5), f4add(a6, a7));
                    t = f4add(f4add(__ldg(&hin4[n * 32 + lane]), s01), s23);
                }
                __nv_bfloat16 hx = __float2bfloat16(t.x), hy = __float2bfloat16(t.y);
                __nv_bfloat16 hz = __float2bfloat16(t.z), hw = __float2bfloat16(t.w);
                unsigned hp0 = pack_bf2(t.x, t.y), hp1 = pack_bf2(t.z, t.w);
                unsigned lp0 = pack_bf2(t.x - __bfloat162float(hx), t.y - __bfloat162float(hy));
                unsigned lp1 = pack_bf2(t.z - __bfloat162float(hz), t.w - __bfloat162float(hw));
                unsigned so = swb(m, lane * 8);
                *(uint2*)(sm + aBuf + so) = make_uint2(hp0, hp1);
                *(uint2*)(sm + aBuf + 16384 + so) = make_uint2(lp0, lp1);
            }
        } else if (wid >= 4 && cons_active) {
            // ---- consumer: MLP1+MLP2+stats on buf[pb^1] ----
            unsigned aBuf = (pb ? SM_ABUF0 : SM_ABUF1);
            unsigned aH = aBuf, aL = aBuf + 16384;
            int cw = wid - 4;
            int m0 = cw * 16;
            int r0 = lane >> 2, cq = (lane & 3) * 2;

            float acc[16][4];
#pragma unroll
            for (int a = 0; a < 16; a++)
#pragma unroll
                for (int c = 0; c < 4; c++) acc[a][c] = 0.f;
            gemm_x3_c(sbase, aH, aL, SM_B1H, SM_B1L, m0, lane, acc);
            __syncwarp();

            // epilogue 1: bias+relu, re-split into own A rows
#pragma unroll
            for (int nt = 0; nt < 16; nt++) {
                int c = nt * 8 + cq;
                float bb0 = bi1[c], bb1 = bi1[c + 1];
                int mA = m0 + r0;
                float v0 = fmaxf(acc[nt][0] + bb0, 0.f);
                float v1 = fmaxf(acc[nt][1] + bb1, 0.f);
                float v2 = fmaxf(acc[nt][2] + bb0, 0.f);
                float v3 = fmaxf(acc[nt][3] + bb1, 0.f);
                __nv_bfloat16 h0 = __float2bfloat16(v0), h1 = __float2bfloat16(v1);
                __nv_bfloat16 h2 = __float2bfloat16(v2), h3 = __float2bfloat16(v3);
                unsigned oA = swb(mA, 2 * c), oB = swb(mA + 8, 2 * c);
                *(unsigned*)(sm + aH + oA) = pack_bf2(v0, v1);
                *(unsigned*)(sm + aL + oA) =
                    pack_bf2(v0 - __bfloat162float(h0), v1 - __bfloat162float(h1));
                *(unsigned*)(sm + aH + oB) = pack_bf2(v2, v3);
                *(unsigned*)(sm + aL + oB) =
                    pack_bf2(v2 - __bfloat162float(h2), v3 - __bfloat162float(h3));
            }
            __syncwarp();

#pragma unroll
            for (int a = 0; a < 16; a++)
#pragma unroll
                for (int c = 0; c < 4; c++) acc[a][c] = 0.f;
            gemm_x3_c(sbase, aH, aL, SM_B2H, SM_B2L, m0, lane, acc);

            // epilogue 2: bias+relu -> gmem; keep for stats
            int nd0 = tc * TM + m0 + r0, nd1 = nd0 + 8;
#pragma unroll
            for (int nt = 0; nt < 16; nt++) {
                int c = nt * 8 + cq;
                float bb0 = bi2[c], bb1 = bi2[c + 1];
                float o0 = fmaxf(acc[nt][0] + bb0, 0.f);
                float o1 = fmaxf(acc[nt][1] + bb1, 0.f);
                float o2 = fmaxf(acc[nt][2] + bb0, 0.f);
                float o3 = fmaxf(acc[nt][3] + bb1, 0.f);
                acc[nt][0] = o0; acc[nt][1] = o1; acc[nt][2] = o2; acc[nt][3] = o3;
                if (nd0 < NN) *(float2*)(h_out + (size_t)nd0 * DD + c) = make_float2(o0, o1);
                if (nd1 < NN) *(float2*)(h_out + (size_t)nd1 * DD + c) = make_float2(o2, o3);
            }

            // fused GraphNorm stats
            {
                int base = tc * TM;
                int gs = g_nodeg[base];
                int lastn = base + TM - 1; if (lastn >= NN) lastn = NN - 1;
                int ge = g_nodeg[lastn];
                int rb0 = (nd0 < NN) ? g_nodeg[nd0] : -1;
                int rb1 = (nd1 < NN) ? g_nodeg[nd1] : -1;
                for (int g = gs; g <= ge; g++) {
#pragma unroll
                    for (int nt = 0; nt < 16; nt++) {
                        float p0 = 0.f, p1 = 0.f, q0 = 0.f, q1 = 0.f;
                        if (rb0 == g) {
                            p0 += acc[nt][0]; q0 += acc[nt][0] * acc[nt][0];
                            p1 += acc[nt][1]; q1 += acc[nt][1] * acc[nt][1];
                        }
                        if (rb1 == g) {
                            p0 += acc[nt][2]; q0 += acc[nt][2] * acc[nt][2];
                            p1 += acc[nt][3]; q1 += acc[nt][3] * acc[nt][3];
                        }
#pragma unroll
                        for (int o = 4; o <= 16; o <<= 1) {
                            p0 += __shfl_xor_sync(0xffffffffu, p0, o);
                            p1 += __shfl_xor_sync(0xffffffffu, p1, o);
                            q0 += __shfl_xor_sync(0xffffffffu, q0, o);
                            q1 += __shfl_xor_sync(0xffffffffu, q1, o);
                        }
                        if (lane < 4) {
                            int c = nt * 8 + lane * 2;
                            scrS[cw * 128 + c] = p0; scrS[cw * 128 + c + 1] = p1;
                            scrQ[cw * 128 + c] = q0; scrQ[cw * 128 + c + 1] = q1;
                        }
                    }
                    BAR_CONS();
                    {
                        int ct = tid - 128;
                        float s = scrS[ct] + scrS[128 + ct] + scrS[256 + ct] + scrS[384 + ct];
                        float q = scrQ[ct] + scrQ[128 + ct] + scrQ[256 + ct] + scrQ[384 + ct];
                        atomicAdd(&g_sum2[par][g * DD + ct], s);
                        atomicAdd(&g_sumsq2[par][g * DD + ct], q);
                    }
                    BAR_CONS();
                }
            }
        }
        __syncthreads();
        tc = prod_active ? tp : -1;
        tp += G;
        pb ^= 1;
    }
}

// ---------------- GraphNorm normalize (+zero next-parity stats, +readout) ----------------
__global__ void k_gnorm2(float* __restrict__ h, const float* __restrict__ w,
                         const float* __restrict__ b, const float* __restrict__ ms,
                         int layer) {
    int par = layer & 1;
    int g = blockIdx.x, c = blockIdx.y, d = threadIdx.x;
    int s = g_gstart[g], n = g_gstart[g + 1] - s;
    int is = s + (n * c) / 8, ie = s + (n * (c + 1)) / 8;
    float cnt = g_countsf[g];
    float m0 = g_sum2[par][g * DD + d] / cnt;
    float a = m0 * ms[d];
    float var = g_sumsq2[par][g * DD + d] / cnt - 2.f * a * m0 + a * a;
    float inv = rsqrtf(var + 1e-5f) * w[d];
    float bb = b[d];
    g_sum2[par ^ 1][g * DD + d] = 0.f;
    g_sumsq2[par ^ 1][g * DD + d] = 0.f;
    float local = 0.f;
    for (int i = is; i < ie; i++) {
        float o = fmaxf((h[(size_t)i * DD + d] - a) * inv + bb, 0.f);
        h[(size_t)i * DD + d] = o;
        local += o;
    }
    if (layer == NL - 1 && ie > is) atomicAdd(&g_gsum[g * DD + d], local);
}

// ---------------- head MLP + log_softmax ----------------
__global__ void k_final(const float* __restrict__ fw1, const float* __restrict__ fb1,
                        const float* __restrict__ fw2, const float* __restrict__ fb2,
                        const float* __restrict__ fw3, const float* __restrict__ fb3,
                        float* __restrict__ out) {
    __shared__ float s0[DD], s1[DD], slog[NC], lse;
    int g = blockIdx.x, d = threadIdx.x;
    s0[d] = g_gsum[g * DD + d];
    __syncthreads();
    float a = fb1[d];
#pragma unroll 4
    for (int k = 0; k < DD; k++) a += s0[k] * fw1[k * DD + d];
    s1[d] = fmaxf(a, 0.f);
    __syncthreads();
    float bv = fb2[d];
#pragma unroll 4
    for (int k = 0; k < DD; k++) bv += s1[k] * fw2[k * DD + d];
    s0[d] = fmaxf(bv, 0.f);
    __syncthreads();
    if (d < NC) {
        float c = fb3[d];
        for (int k = 0; k < DD; k++) c += s0[k] * fw3[k * NC + d];
        slog[d] = c;
    }
    __syncthreads();
    if (d == 0) {
        float mx = -1e30f;
        for (int c = 0; c < NC; c++) mx = fmaxf(mx, slog[c]);
        float se = 0.f;
        for (int c = 0; c < NC; c++) se += expf(slog[c] - mx);
        lse = mx + logf(se);
    }
    __syncthreads();
    if (d < NC) out[g * NC + d] = slog[d] - lse;
}

// ---------------- launch ----------------
extern "C" void kernel_launch(void* const* d_in, const int* in_sizes, int n_in,
                              void* d_out, int out_size) {
    const float* x   = (const float*)d_in[0];
    const float* gw1 = (const float*)d_in[1];
    const float* gb1 = (const float*)d_in[2];
    const float* gw2 = (const float*)d_in[3];
    const float* gb2 = (const float*)d_in[4];
    const float* gnw = (const float*)d_in[5];
    const float* gnb = (const float*)d_in[6];
    const float* gns = (const float*)d_in[7];
    const float* fw1 = (const float*)d_in[8];
    const float* fb1 = (const float*)d_in[9];
    const float* fw2 = (const float*)d_in[10];
    const float* fb2 = (const float*)d_in[11];
    const float* fw3 = (const float*)d_in[12];
    const float* fb3 = (const float*)d_in[13];
    const void*  ei  = d_in[14];
    const void*  bat = d_in[15];
    float* out = (float*)d_out;

    cudaFuncSetAttribute(k_layer, cudaFuncAttributeMaxDynamicSharedMemorySize, DYN_SMEM);
    int nsm = 148;
    cudaDeviceGetAttribute(&nsm, cudaDevAttrMultiProcessorCount, 0);

    void* p = nullptr;
    cudaGetSymbolAddress(&p, g_hbuf);
    float* hA = (float*)p;
    float* hB = hA + (size_t)NN * DD;

    k_pre<<<nsm, 256>>>(ei, bat);

    const float* cur = x;
    for (int l = 0; l < NL; l++) {
        float* ob = (l & 1) ? hB : hA;
        k_layer<<<nsm, 256, DYN_SMEM>>>(cur, ob,
                                        gw1 + l * DD * DD, gb1 + l * DD,
                                        gw2 + l * DD * DD, gb2 + l * DD, l);
        k_gnorm2<<<dim3(NG, 8), DD>>>(ob, gnw + l * DD, gnb + l * DD, gns + l * DD, l);
        cur = ob;
    }
    k_final<<<NG, DD>>>(fw1, fb1, fw2, fb2, fw3, fb3, out);
}

// round 10
// speedup vs baseline: 1.7487x; 1.7487x over previous
#include <cuda_runtime.h>
#include <cuda_bf16.h>

#define NN 50000
#define NE 800000
#define NG 128
#define DD 128
#define NL 4
#define NC 10
#define TM 128
#define NUM_TILES ((NN + TM - 1) / TM)   // 391
#define NTHR 512

// ---------------- device scratch ----------------
__device__ float g_hbuf[2][NN * DD];
__device__ int   g_deg[NN];
__device__ int   g_rowptr[NN + 1];
__device__ int   g_cursor[NN];
__device__ int   g_colsrc[NE];
__device__ int   g_gstart[NG + 1];
__device__ int   g_nodeg[NN];
__device__ float g_countsf[NG];
__device__ float g_sum2[2][NG * DD];
__device__ float g_sumsq2[2][NG * DD];
__device__ float g_gsum[NG * DD];
__device__ int   g_tilectr[NL];
__device__ int   g_blocksum[256];
__device__ int   g_blockpre[256];
__device__ int   g_ei64, g_b64;
__device__ unsigned g_sync_count = 0;
__device__ volatile unsigned g_sync_gen = 0;

// ---------------- helpers ----------------
__device__ __forceinline__ unsigned smem_u32(const void* p) {
    unsigned a;
    asm("{ .reg .u64 t; cvta.to.shared.u64 t, %1; cvt.u32.u64 %0, t; }" : "=r"(a) : "l"(p));
    return a;
}
// swizzled byte offset inside a [128 rows x 256 bytes] bf16 tile
__device__ __forceinline__ unsigned swb(int r, int kb) {
    unsigned w = (unsigned)kb & 127u;
    unsigned sw = w ^ (((unsigned)r & 7u) << 4);
    return (unsigned)r * 256u + ((unsigned)kb & 128u) + sw;
}
__device__ __forceinline__ unsigned pack_bf2(float a, float b) {
    __nv_bfloat162 p = __floats2bfloat162_rn(a, b);
    return *reinterpret_cast<unsigned*>(&p);
}
__device__ __forceinline__ float4 f4add(float4 a, float4 b) {
    a.x += b.x; a.y += b.y; a.z += b.z; a.w += b.w; return a;
}
__device__ __forceinline__ void ldsm4(unsigned* r, unsigned addr) {
    asm volatile("ldmatrix.sync.aligned.m8n8.x4.shared.b16 {%0,%1,%2,%3}, [%4];"
        : "=r"(r[0]), "=r"(r[1]), "=r"(r[2]), "=r"(r[3]) : "r"(addr));
}
__device__ __forceinline__ void ldsm2(unsigned* r, unsigned addr) {
    asm volatile("ldmatrix.sync.aligned.m8n8.x2.shared.b16 {%0,%1}, [%2];"
        : "=r"(r[0]), "=r"(r[1]) : "r"(addr));
}
__device__ __forceinline__ void mma16816(float* d, const unsigned* a, const unsigned* b) {
    asm volatile("mma.sync.aligned.m16n8k16.row.col.f32.bf16.bf16.f32 "
        "{%0,%1,%2,%3}, {%4,%5,%6,%7}, {%8,%9}, {%0,%1,%2,%3};"
        : "+f"(d[0]), "+f"(d[1]), "+f"(d[2]), "+f"(d[3])
        : "r"(a[0]), "r"(a[1]), "r"(a[2]), "r"(a[3]), "r"(b[0]), "r"(b[1]));
}

// ---------------- grid-wide barrier (all blocks resident) ----------------
__device__ __forceinline__ void gsync() {
    __syncthreads();
    if (threadIdx.x == 0) {
        unsigned gen = g_sync_gen;
        __threadfence();
        if (atomicAdd(&g_sync_count, 1u) == gridDim.x - 1) {
            g_sync_count = 0;
            __threadfence();
            g_sync_gen = gen + 1;
        } else {
            while (g_sync_gen == gen) { }
        }
        __threadfence();
    }
    __syncthreads();
}

// ---------------- fused persistent preprocessing ----------------
__global__ void __launch_bounds__(256) k_pre(const void* __restrict__ ei,
                                             const void* __restrict__ bat) {
    __shared__ int sscan[256];
    int tid = threadIdx.x, bid = blockIdx.x;
    int gtid = bid * 256 + tid, gsz = gridDim.x * 256;

    // phase 1: dtype detect + zero arrays
    if (bid == 0 && tid < 32) {
        const int* ei_w = (const int*)ei;
        const int* b_w = (const int*)bat;
        int ok1 = (ei_w[2 * tid + 1] == 0) && (ei_w[2 * (tid + 32) + 1] == 0);
        int a = __all_sync(0xffffffffu, ok1);
        int ok2 = (b_w[20001 + 2 * tid] == 0) && (b_w[20065 + 2 * tid] == 0);
        int b = __all_sync(0xffffffffu, ok2);
        if (tid == 0) { g_ei64 = a; g_b64 = b; }
    }
    for (int i = gtid; i < NN; i += gsz) g_deg[i] = 0;
    for (int i = gtid; i < NG * DD; i += gsz) {
        g_sum2[0][i] = 0.f; g_sum2[1][i] = 0.f;
        g_sumsq2[0][i] = 0.f; g_sumsq2[1][i] = 0.f;
        g_gsum[i] = 0.f;
    }
    if (gtid < NL) g_tilectr[gtid] = 0;
    gsync();

    // phase 2: graph bounds + degree histogram
    int e64 = g_ei64, b64 = g_b64;
    for (int i = gtid; i < NN; i += gsz) {
        int bi = b64 ? (int)((const long long*)bat)[i] : ((const int*)bat)[i];
        g_nodeg[i] = bi;
        int prev = -1;
        if (i > 0)
            prev = b64 ? (int)((const long long*)bat)[i - 1] : ((const int*)bat)[i - 1];
        for (int g = prev + 1; g <= bi; g++) g_gstart[g] = i;
        if (i == NN - 1)
            for (int g = bi + 1; g <= NG; g++) g_gstart[g] = NN;
    }
    for (int e = gtid; e < NE; e += gsz) {
        int d = e64 ? (int)((const long long*)ei)[NE + e] : ((const int*)ei)[NE + e];
        atomicAdd(&g_deg[d], 1);
    }
    gsync();

    // phase 3a: per-thread chunk sums + block scan
    const int CH = (NN + gsz - 1) / gsz;
    int base = gtid * CH;
    int s = 0;
    for (int j = 0; j < CH; j++) { int idx = base + j; if (idx < NN) s += g_deg[idx]; }
    sscan[tid] = s;
    __syncthreads();
    for (int off = 1; off < 256; off <<= 1) {
        int v = (tid >= off) ? sscan[tid - off] : 0;
        __syncthreads();
        sscan[tid] += v;
        __syncthreads();
    }
    int thr_excl = sscan[tid] - s;
    if (tid == 255) g_blocksum[bid] = sscan[255];
    gsync();

    // phase 3b: block 0 scans block totals (exclusive)
    if (bid == 0) {
        int v = (tid < (int)gridDim.x) ? g_blocksum[tid] : 0;
        sscan[tid] = v;
        __syncthreads();
        for (int off = 1; off < 256; off <<= 1) {
            int u = (tid >= off) ? sscan[tid - off] : 0;
            __syncthreads();
            sscan[tid] += u;
            __syncthreads();
        }
        if (tid < (int)gridDim.x) g_blockpre[tid] = sscan[tid] - v;
    }
    gsync();

    // phase 3c: write rowptr/cursor; counts
    int off = g_blockpre[bid] + thr_excl;
    for (int j = 0; j < CH; j++) {
        int idx = base + j;
        if (idx < NN) { g_rowptr[idx] = off; g_cursor[idx] = off; off += g_deg[idx]; }
    }
    if (gtid == 0) g_rowptr[NN] = NE;
    if (gtid < NG)
        g_countsf[gtid] = fmaxf((float)(g_gstart[gtid + 1] - g_gstart[gtid]), 1.f);
    gsync();

    // phase 4: fill CSR columns
    for (int e = gtid; e < NE; e += gsz) {
        int src, dst;
        if (e64) {
            src = (int)((const long long*)ei)[e];
            dst = (int)((const long long*)ei)[NE + e];
        } else {
            src = ((const int*)ei)[e];
            dst = ((const int*)ei)[NE + e];
        }
        g_colsrc[atomicAdd(&g_cursor[dst], 1)] = src;
    }
}

// ---------------- fused layer: gather + bf16x3 mma.sync + GN stats (512 thr) ----------------
#define SM_B1H 0
#define SM_B1L 32768
#define SM_B2H 65536
#define SM_B2L 98304
#define SM_A0  131072
#define SM_A1  163840
#define SM_BI1 196608
#define SM_BI2 197120
#define DYN_SMEM (197632 + 1024)

// bf16x3 warp GEMM: 32 rows (m0) x 32 cols (n0) x K=128
__device__ __forceinline__ void gemm_x3(unsigned sbase, unsigned aH, unsigned aL,
                                        unsigned bH, unsigned bL,
                                        int m0, int n0, int lane,
                                        float acc[2][4][4]) {
    int aRow = lane & 15;
    int aKoff = (lane >> 4) * 16;
    int bRow = lane & 7;
    int bKoff = ((lane >> 3) & 1) * 16;
#pragma unroll 1
    for (int ks = 0; ks < 8; ks++) {
        int kb = ks * 32;
        unsigned ah0[4], ah1[4], al0[4], al1[4];
        ldsm4(ah0, sbase + aH + swb(m0 + aRow, kb + aKoff));
        ldsm4(ah1, sbase + aH + swb(m0 + 16 + aRow, kb + aKoff));
        ldsm4(al0, sbase + aL + swb(m0 + aRow, kb + aKoff));
        ldsm4(al1, sbase + aL + swb(m0 + 16 + aRow, kb + aKoff));
#pragma unroll
        for (int nt = 0; nt < 4; nt++) {
            unsigned bh[2], bl[2];
            ldsm2(bh, sbase + bH + swb(n0 + nt * 8 + bRow, kb + bKoff));
            ldsm2(bl, sbase + bL + swb(n0 + nt * 8 + bRow, kb + bKoff));
            mma16816(acc[0][nt], ah0, bh);
            mma16816(acc[1][nt], ah1, bh);
            mma16816(acc[0][nt], al0, bh);
            mma16816(acc[1][nt], al1, bh);
            mma16816(acc[0][nt], ah0, bl);
            mma16816(acc[1][nt], ah1, bl);
        }
    }
}

__global__ void __launch_bounds__(NTHR, 1) k_layer(
    const float* __restrict__ h_in, float* __restrict__ h_out,
    const float* __restrict__ W1, const float* __restrict__ B1,
    const float* __restrict__ W2, const float* __restrict__ B2,
    int layer)
{
    extern __shared__ char smraw[];
    char* sm = (char*)(((unsigned long long)smraw + 1023ull) & ~1023ull);
    unsigned sbase = smem_u32(sm);
    __shared__ int s_tile;
    int tid = threadIdx.x, lane = tid & 31, wid = tid >> 5;
    int par = layer & 1;

    // stage W^T hi/lo (swizzled) + biases
    for (int idx = tid; idx < DD * DD; idx += NTHR) {
        int k = idx >> 7, n = idx & 127;
        float v1 = W1[idx], v2 = W2[idx];
        unsigned o = swb(n, 2 * k);
        __nv_bfloat16 h1 = __float2bfloat16(v1), h2 = __float2bfloat16(v2);
        *(__nv_bfloat16*)(sm + SM_B1H + o) = h1;
        *(__nv_bfloat16*)(sm + SM_B1L + o) = __float2bfloat16(v1 - __bfloat162float(h1));
        *(__nv_bfloat16*)(sm + SM_B2H + o) = h2;
        *(__nv_bfloat16*)(sm + SM_B2L + o) = __float2bfloat16(v2 - __bfloat162float(h2));
    }
    if (tid < 128) {
        ((float*)(sm + SM_BI1))[tid] = B1[tid];
        ((float*)(sm + SM_BI2))[tid] = B2[tid];
    }
    __syncthreads();

    const float4* hin4 = (const float4*)h_in;
    const float* bi1 = (const float*)(sm + SM_BI1);
    const float* bi2 = (const float*)(sm + SM_BI2);

    int warpM = wid & 3, warpN = wid >> 2;       // 4 x 4 warp grid
    int m0 = warpM * 32, n0 = warpN * 32;
    int r0 = lane >> 2, cq = (lane & 3) * 2;

    for (;;) {
        if (tid == 0) s_tile = atomicAdd(&g_tilectr[layer], 1);
        __syncthreads();
        int tile = s_tile;
        if (tile >= NUM_TILES) break;

        // ---- gather: 8 nodes/warp, 8 float4 loads in flight ----
#pragma unroll 1
        for (int mi = 0; mi < 8; mi++) {
            int m = wid * 8 + mi;
            int n = tile * TM + m;
            float4 t = make_float4(0.f, 0.f, 0.f, 0.f);
            if (n < NN) {
                float4 a0 = t, a1 = t, a2 = t, a3 = t, a4 = t, a5 = t, a6 = t, a7 = t;
                int beg = g_rowptr[n], end = g_rowptr[n + 1];
                int e = beg;
                for (; e + 8 <= end; e += 8) {
                    int s0 = g_colsrc[e],     s1 = g_colsrc[e + 1];
                    int s2 = g_colsrc[e + 2], s3 = g_colsrc[e + 3];
                    int s4 = g_colsrc[e + 4], s5 = g_colsrc[e + 5];
                    int s6 = g_colsrc[e + 6], s7 = g_colsrc[e + 7];
                    a0 = f4add(a0, __ldg(&hin4[s0 * 32 + lane]));
                    a1 = f4add(a1, __ldg(&hin4[s1 * 32 + lane]));
                    a2 = f4add(a2, __ldg(&hin4[s2 * 32 + lane]));
                    a3 = f4add(a3, __ldg(&hin4[s3 * 32 + lane]));
                    a4 = f4add(a4, __ldg(&hin4[s4 * 32 + lane]));
                    a5 = f4add(a5, __ldg(&hin4[s5 * 32 + lane]));
                    a6 = f4add(a6, __ldg(&hin4[s6 * 32 + lane]));
                    a7 = f4add(a7, __ldg(&hin4[s7 * 32 + lane]));
                }
                if (e + 4 <= end) {
                    int s0 = g_colsrc[e],     s1 = g_colsrc[e + 1];
                    int s2 = g_colsrc[e + 2], s3 = g_colsrc[e + 3];
                    a0 = f4add(a0, __ldg(&hin4[s0 * 32 + lane]));
                    a1 = f4add(a1, __ldg(&hin4[s1 * 32 + lane]));
                    a2 = f4add(a2, __ldg(&hin4[s2 * 32 + lane]));
                    a3 = f4add(a3, __ldg(&hin4[s3 * 32 + lane]));
                    e += 4;
                }
                for (; e < end; e++)
                    a0 = f4add(a0, __ldg(&hin4[g_colsrc[e] * 32 + lane]));
                float4 s01 = f4add(f4add(a0, a1), f4add(a2, a3));
                float4 s23 = f4add(f4add(a4, a5), f4add(a6, a7));
                t = f4add(f4add(__ldg(&hin4[n * 32 + lane]), s01), s23);
            }
            __nv_bfloat16 hx = __float2bfloat16(t.x), hy = __float2bfloat16(t.y);
            __nv_bfloat16 hz = __float2bfloat16(t.z), hw = __float2bfloat16(t.w);
            unsigned hp0 = pack_bf2(t.x, t.y), hp1 = pack_bf2(t.z, t.w);
            unsigned lp0 = pack_bf2(t.x - __bfloat162float(hx), t.y - __bfloat162float(hy));
            unsigned lp1 = pack_bf2(t.z - __bfloat162float(hz), t.w - __bfloat162float(hw));
            unsigned so = swb(m, lane * 8);
            *(uint2*)(sm + SM_A0 + so) = make_uint2(hp0, hp1);
            *(uint2*)(sm + SM_A1 + so) = make_uint2(lp0, lp1);
        }
        __syncthreads();

        // ---- MLP1 ----
        float acc[2][4][4];
#pragma unroll
        for (int a = 0; a < 2; a++)
#pragma unroll
            for (int b = 0; b < 4; b++)
#pragma unroll
                for (int c = 0; c < 4; c++) acc[a][b][c] = 0.f;
        gemm_x3(sbase, SM_A0, SM_A1, SM_B1H, SM_B1L, m0, n0, lane, acc);
        __syncthreads();

        // ---- epilogue 1: bias+relu, re-split into A ----
#pragma unroll
        for (int mt = 0; mt < 2; mt++) {
#pragma unroll
            for (int nt = 0; nt < 4; nt++) {
                int c = n0 + nt * 8 + cq;
                float bb0 = bi1[c], bb1 = bi1[c + 1];
                int mA = m0 + mt * 16 + r0;
                float v0 = fmaxf(acc[mt][nt][0] + bb0, 0.f);
                float v1 = fmaxf(acc[mt][nt][1] + bb1, 0.f);
                float v2 = fmaxf(acc[mt][nt][2] + bb0, 0.f);
                float v3 = fmaxf(acc[mt][nt][3] + bb1, 0.f);
                __nv_bfloat16 h0 = __float2bfloat16(v0), h1 = __float2bfloat16(v1);
                __nv_bfloat16 h2 = __float2bfloat16(v2), h3 = __float2bfloat16(v3);
                unsigned oA = swb(mA, 2 * c), oB = swb(mA + 8, 2 * c);
                *(unsigned*)(sm + SM_A0 + oA) = pack_bf2(v0, v1);
                *(unsigned*)(sm + SM_A1 + oA) =
                    pack_bf2(v0 - __bfloat162float(h0), v1 - __bfloat162float(h1));
                *(unsigned*)(sm + SM_A0 + oB) = pack_bf2(v2, v3);
                *(unsigned*)(sm + SM_A1 + oB) =
                    pack_bf2(v2 - __bfloat162float(h2), v3 - __bfloat162float(h3));
            }
        }
        __syncthreads();

        // ---- MLP2 ----
#pragma unroll
        for (int a = 0; a < 2; a++)
#pragma unroll
            for (int b = 0; b < 4; b++)
#pragma unroll
                for (int c = 0; c < 4; c++) acc[a][b][c] = 0.f;
        gemm_x3(sbase, SM_A0, SM_A1, SM_B2H, SM_B2L, m0, n0, lane, acc);
        __syncthreads();   // A reads done before stats scratch / next gather

        // ---- epilogue 2: bias+relu -> gmem; keep in acc for stats ----
#pragma unroll
        for (int mt = 0; mt < 2; mt++) {
#pragma unroll
            for (int nt = 0; nt < 4; nt++) {
                int c = n0 + nt * 8 + cq;
                float bb0 = bi2[c], bb1 = bi2[c + 1];
                int mA = m0 + mt * 16 + r0;
                int nd0 = tile * TM + mA, nd1 = nd0 + 8;
                float o0 = fmaxf(acc[mt][nt][0] + bb0, 0.f);
                float o1 = fmaxf(acc[mt][nt][1] + bb1, 0.f);
                float o2 = fmaxf(acc[mt][nt][2] + bb0, 0.f);
                float o3 = fmaxf(acc[mt][nt][3] + bb1, 0.f);
                acc[mt][nt][0] = o0; acc[mt][nt][1] = o1;
                acc[mt][nt][2] = o2; acc[mt][nt][3] = o3;
                if (nd0 < NN) *(float2*)(h_out + (size_t)nd0 * DD + c) = make_float2(o0, o1);
                if (nd1 < NN) *(float2*)(h_out + (size_t)nd1 * DD + c) = make_float2(o2, o3);
            }
        }

        // ---- fused GraphNorm stats ----
        {
            int base = tile * TM;
            int gs = g_nodeg[base];
            int lastn = base + TM - 1; if (lastn >= NN) lastn = NN - 1;
            int ge = g_nodeg[lastn];
            int rb[4];
#pragma unroll
            for (int j = 0; j < 4; j++) {
                int nd = base + m0 + j * 8 + r0;
                rb[j] = (nd < NN) ? g_nodeg[nd] : -1;
            }
            float* scrS = (float*)(sm + SM_A0);   // [4 warpM][128] floats
            float* scrQ = scrS + 512;
            for (int g = gs; g <= ge; g++) {
#pragma unroll
                for (int nt = 0; nt < 4; nt++) {
                    float p0 = 0.f, p1 = 0.f, q0 = 0.f, q1 = 0.f;
#pragma unroll
                    for (int mt = 0; mt < 2; mt++) {
                        if (rb[mt * 2 + 0] == g) {
                            float v0 = acc[mt][nt][0], v1 = acc[mt][nt][1];
                            p0 += v0; q0 += v0 * v0; p1 += v1; q1 += v1 * v1;
                        }
                        if (rb[mt * 2 + 1] == g) {
                            float v0 = acc[mt][nt][2], v1 = acc[mt][nt][3];
                            p0 += v0; q0 += v0 * v0; p1 += v1; q1 += v1 * v1;
                        }
                    }
#pragma unroll
                    for (int o = 4; o <= 16; o <<= 1) {
                        p0 += __shfl_xor_sync(0xffffffffu, p0, o);
                        p1 += __shfl_xor_sync(0xffffffffu, p1, o);
                        q0 += __shfl_xor_sync(0xffffffffu, q0, o);
                        q1 += __shfl_xor_sync(0xffffffffu, q1, o);
                    }
                    if (r0 == 0) {   // lanes 0-3
                        int c = n0 + nt * 8 + cq;
                        scrS[warpM * 128 + c]     = p0;
                        scrS[warpM * 128 + c + 1] = p1;
                        scrQ[warpM * 128 + c]     = q0;
                        scrQ[warpM * 128 + c + 1] = q1;
                    }
                }
                __syncthreads();
                if (tid < 128) {
                    float s = scrS[tid] + scrS[128 + tid] + scrS[256 + tid] + scrS[384 + tid];
                    atomicAdd(&g_sum2[par][g * DD + tid], s);
                } else if (tid < 256) {
                    int d2 = tid - 128;
                    float s = scrQ[d2] + scrQ[128 + d2] + scrQ[256 + d2] + scrQ[384 + d2];
                    atomicAdd(&g_sumsq2[par][g * DD + d2], s);
                }
                __syncthreads();
            }
        }
    }
}

// ---------------- GraphNorm normalize (+zero next-parity stats, +readout) ----------------
__global__ void k_gnorm2(float* __restrict__ h, const float* __restrict__ w,
                         const float* __restrict__ b, const float* __restrict__ ms,
                         int layer) {
    int par = layer & 1;
    int g = blockIdx.x, c = blockIdx.y, d = threadIdx.x;
    int s = g_gstart[g], n = g_gstart[g + 1] - s;
    int is = s + (n * c) / 8, ie = s + (n * (c + 1)) / 8;
    float cnt = g_countsf[g];
    float m0 = g_sum2[par][g * DD + d] / cnt;
    float a = m0 * ms[d];
    float var = g_sumsq2[par][g * DD + d] / cnt - 2.f * a * m0 + a * a;
    float inv = rsqrtf(var + 1e-5f) * w[d];
    float bb = b[d];
    g_sum2[par ^ 1][g * DD + d] = 0.f;
    g_sumsq2[par ^ 1][g * DD + d] = 0.f;
    float local = 0.f;
    for (int i = is; i < ie; i++) {
        float o = fmaxf((h[(size_t)i * DD + d] - a) * inv + bb, 0.f);
        h[(size_t)i * DD + d] = o;
        local += o;
    }
    if (layer == NL - 1 && ie > is) atomicAdd(&g_gsum[g * DD + d], local);
}

// ---------------- head MLP + log_softmax ----------------
__global__ void k_final(const float* __restrict__ fw1, const float* __restrict__ fb1,
                        const float* __restrict__ fw2, const float* __restrict__ fb2,
                        const float* __restrict__ fw3, const float* __restrict__ fb3,
                        float* __restrict__ out) {
    __shared__ float s0[DD], s1[DD], slog[NC], lse;
    int g = blockIdx.x, d = threadIdx.x;
    s0[d] = g_gsum[g * DD + d];
    __syncthreads();
    float a = fb1[d];
#pragma unroll 4
    for (int k = 0; k < DD; k++) a += s0[k] * fw1[k * DD + d];
    s1[d] = fmaxf(a, 0.f);
    __syncthreads();
    float bv = fb2[d];
#pragma unroll 4
    for (int k = 0; k < DD; k++) bv += s1[k] * fw2[k * DD + d];
    s0[d] = fmaxf(bv, 0.f);
    __syncthreads();
    if (d < NC) {
        float c = fb3[d];
        for (int k = 0; k < DD; k++) c += s0[k] * fw3[k * NC + d];
        slog[d] = c;
    }
    __syncthreads();
    if (d == 0) {
        float mx = -1e30f;
        for (int c = 0; c < NC; c++) mx = fmaxf(mx, slog[c]);
        float se = 0.f;
        for (int c = 0; c < NC; c++) se += expf(slog[c] - mx);
        lse = mx + logf(se);
    }
    __syncthreads();
    if (d < NC) out[g * NC + d] = slog[d] - lse;
}

// ---------------- launch ----------------
extern "C" void kernel_launch(void* const* d_in, const int* in_sizes, int n_in,
                              void* d_out, int out_size) {
    const float* x   = (const float*)d_in[0];
    const float* gw1 = (const float*)d_in[1];
    const float* gb1 = (const float*)d_in[2];
    const float* gw2 = (const float*)d_in[3];
    const float* gb2 = (const float*)d_in[4];
    const float* gnw = (const float*)d_in[5];
    const float* gnb = (const float*)d_in[6];
    const float* gns = (const float*)d_in[7];
    const float* fw1 = (const float*)d_in[8];
    const float* fb1 = (const float*)d_in[9];
    const float* fw2 = (const float*)d_in[10];
    const float* fb2 = (const float*)d_in[11];
    const float* fw3 = (const float*)d_in[12];
    const float* fb3 = (const float*)d_in[13];
    const void*  ei  = d_in[14];
    const void*  bat = d_in[15];
    float* out = (float*)d_out;

    cudaFuncSetAttribute(k_layer, cudaFuncAttributeMaxDynamicSharedMemorySize, DYN_SMEM);
    int nsm = 148;
    cudaDeviceGetAttribute(&nsm, cudaDevAttrMultiProcessorCount, 0);

    void* p = nullptr;
    cudaGetSymbolAddress(&p, g_hbuf);
    float* hA = (float*)p;
    float* hB = hA + (size_t)NN * DD;

    k_pre<<<nsm, 256>>>(ei, bat);

    const float* cur = x;
    for (int l = 0; l < NL; l++) {
        float* ob = (l & 1) ? hB : hA;
        k_layer<<<nsm, NTHR, DYN_SMEM>>>(cur, ob,
                                         gw1 + l * DD * DD, gb1 + l * DD,
                                         gw2 + l * DD * DD, gb2 + l * DD, l);
        k_gnorm2<<<dim3(NG, 8), DD>>>(ob, gnw + l * DD, gnb + l * DD, gns + l * DD, l);
        cur = ob;
    }
    k_final<<<NG, DD>>>(fw1, fb1, fw2, fb2, fw3, fb3, out);
}

// round 11
// speedup vs baseline: 1.8430x; 1.0540x over previous
#include <cuda_runtime.h>
#include <cuda_bf16.h>

#define NN 50000
#define NE 800000
#define NG 128
#define DD 128
#define NL 4
#define NC 10
#define TM 128
#define NUM_TILES ((NN + TM - 1) / TM)   // 391
#define NTHR 1024

// ---------------- device scratch ----------------
__device__ float g_hbuf[2][NN * DD];
__device__ int   g_deg[NN];
__device__ int   g_rowptr[NN + 1];
__device__ int   g_cursor[NN];
__device__ int   g_colsrc[NE];
__device__ int   g_gstart[NG + 1];
__device__ int   g_nodeg[NN];
__device__ float g_countsf[NG];
__device__ float g_sum2[2][NG * DD];
__device__ float g_sumsq2[2][NG * DD];
__device__ float g_gsum[NG * DD];
__device__ int   g_tilectr[NL];
__device__ int   g_blocksum[256];
__device__ int   g_blockpre[256];
__device__ int   g_ei64, g_b64;
__device__ unsigned g_sync_count = 0;
__device__ volatile unsigned g_sync_gen = 0;

// ---------------- helpers ----------------
__device__ __forceinline__ unsigned smem_u32(const void* p) {
    unsigned a;
    asm("{ .reg .u64 t; cvta.to.shared.u64 t, %1; cvt.u32.u64 %0, t; }" : "=r"(a) : "l"(p));
    return a;
}
// swizzled byte offset inside a [128 rows x 256 bytes] bf16 tile
__device__ __forceinline__ unsigned swb(int r, int kb) {
    unsigned w = (unsigned)kb & 127u;
    unsigned sw = w ^ (((unsigned)r & 7u) << 4);
    return (unsigned)r * 256u + ((unsigned)kb & 128u) + sw;
}
__device__ __forceinline__ unsigned pack_bf2(float a, float b) {
    __nv_bfloat162 p = __floats2bfloat162_rn(a, b);
    return *reinterpret_cast<unsigned*>(&p);
}
__device__ __forceinline__ float4 f4add(float4 a, float4 b) {
    a.x += b.x; a.y += b.y; a.z += b.z; a.w += b.w; return a;
}
__device__ __forceinline__ void ldsm4(unsigned* r, unsigned addr) {
    asm volatile("ldmatrix.sync.aligned.m8n8.x4.shared.b16 {%0,%1,%2,%3}, [%4];"
        : "=r"(r[0]), "=r"(r[1]), "=r"(r[2]), "=r"(r[3]) : "r"(addr));
}
__device__ __forceinline__ void mma16816(float* d, const unsigned* a, const unsigned* b) {
    asm volatile("mma.sync.aligned.m16n8k16.row.col.f32.bf16.bf16.f32 "
        "{%0,%1,%2,%3}, {%4,%5,%6,%7}, {%8,%9}, {%0,%1,%2,%3};"
        : "+f"(d[0]), "+f"(d[1]), "+f"(d[2]), "+f"(d[3])
        : "r"(a[0]), "r"(a[1]), "r"(a[2]), "r"(a[3]), "r"(b[0]), "r"(b[1]));
}

// ---------------- grid-wide barrier (all blocks resident) ----------------
__device__ __forceinline__ void gsync() {
    __syncthreads();
    if (threadIdx.x == 0) {
        unsigned gen = g_sync_gen;
        __threadfence();
        if (atomicAdd(&g_sync_count, 1u) == gridDim.x - 1) {
            g_sync_count = 0;
            __threadfence();
            g_sync_gen = gen + 1;
        } else {
            while (g_sync_gen == gen) { }
        }
        __threadfence();
    }
    __syncthreads();
}

// ---------------- fused persistent preprocessing ----------------
__global__ void __launch_bounds__(256) k_pre(const void* __restrict__ ei,
                                             const void* __restrict__ bat) {
    __shared__ int sscan[256];
    int tid = threadIdx.x, bid = blockIdx.x;
    int gtid = bid * 256 + tid, gsz = gridDim.x * 256;

    // phase 1: dtype detect + zero arrays
    if (bid == 0 && tid < 32) {
        const int* ei_w = (const int*)ei;
        const int* b_w = (const int*)bat;
        int ok1 = (ei_w[2 * tid + 1] == 0) && (ei_w[2 * (tid + 32) + 1] == 0);
        int a = __all_sync(0xffffffffu, ok1);
        int ok2 = (b_w[20001 + 2 * tid] == 0) && (b_w[20065 + 2 * tid] == 0);
        int b = __all_sync(0xffffffffu, ok2);
        if (tid == 0) { g_ei64 = a; g_b64 = b; }
    }
    for (int i = gtid; i < NN; i += gsz) g_deg[i] = 0;
    for (int i = gtid; i < NG * DD; i += gsz) {
        g_sum2[0][i] = 0.f; g_sum2[1][i] = 0.f;
        g_sumsq2[0][i] = 0.f; g_sumsq2[1][i] = 0.f;
        g_gsum[i] = 0.f;
    }
    if (gtid < NL) g_tilectr[gtid] = 0;
    gsync();

    // phase 2: graph bounds + degree histogram
    int e64 = g_ei64, b64 = g_b64;
    for (int i = gtid; i < NN; i += gsz) {
        int bi = b64 ? (int)((const long long*)bat)[i] : ((const int*)bat)[i];
        g_nodeg[i] = bi;
        int prev = -1;
        if (i > 0)
            prev = b64 ? (int)((const long long*)bat)[i - 1] : ((const int*)bat)[i - 1];
        for (int g = prev + 1; g <= bi; g++) g_gstart[g] = i;
        if (i == NN - 1)
            for (int g = bi + 1; g <= NG; g++) g_gstart[g] = NN;
    }
    for (int e = gtid; e < NE; e += gsz) {
        int d = e64 ? (int)((const long long*)ei)[NE + e] : ((const int*)ei)[NE + e];
        atomicAdd(&g_deg[d], 1);
    }
    gsync();

    // phase 3a: per-thread chunk sums + block scan
    const int CH = (NN + gsz - 1) / gsz;
    int base = gtid * CH;
    int s = 0;
    for (int j = 0; j < CH; j++) { int idx = base + j; if (idx < NN) s += g_deg[idx]; }
    sscan[tid] = s;
    __syncthreads();
    for (int off = 1; off < 256; off <<= 1) {
        int v = (tid >= off) ? sscan[tid - off] : 0;
        __syncthreads();
        sscan[tid] += v;
        __syncthreads();
    }
    int thr_excl = sscan[tid] - s;
    if (tid == 255) g_blocksum[bid] = sscan[255];
    gsync();

    // phase 3b: block 0 scans block totals (exclusive)
    if (bid == 0) {
        int v = (tid < (int)gridDim.x) ? g_blocksum[tid] : 0;
        sscan[tid] = v;
        __syncthreads();
        for (int off = 1; off < 256; off <<= 1) {
            int u = (tid >= off) ? sscan[tid - off] : 0;
            __syncthreads();
            sscan[tid] += u;
            __syncthreads();
        }
        if (tid < (int)gridDim.x) g_blockpre[tid] = sscan[tid] - v;
    }
    gsync();

    // phase 3c: write rowptr/cursor; counts
    int off = g_blockpre[bid] + thr_excl;
    for (int j = 0; j < CH; j++) {
        int idx = base + j;
        if (idx < NN) { g_rowptr[idx] = off; g_cursor[idx] = off; off += g_deg[idx]; }
    }
    if (gtid == 0) g_rowptr[NN] = NE;
    if (gtid < NG)
        g_countsf[gtid] = fmaxf((float)(g_gstart[gtid + 1] - g_gstart[gtid]), 1.f);
    gsync();

    // phase 4: fill CSR columns
    for (int e = gtid; e < NE; e += gsz) {
        int src, dst;
        if (e64) {
            src = (int)((const long long*)ei)[e];
            dst = (int)((const long long*)ei)[NE + e];
        } else {
            src = ((const int*)ei)[e];
            dst = ((const int*)ei)[NE + e];
        }
        g_colsrc[atomicAdd(&g_cursor[dst], 1)] = src;
    }
}

// ---------------- fused layer: gather + bf16x3 mma.sync + GN stats (1024 thr) ----------------
#define SM_B1H 0
#define SM_B1L 32768
#define SM_B2H 65536
#define SM_B2L 98304
#define SM_A0  131072
#define SM_A1  163840
#define SM_BI1 196608
#define SM_BI2 197120
#define DYN_SMEM (197632 + 1024)

// bf16x3 warp GEMM: 16 rows (m0) x 32 cols (n0) x K=128, acc = 16 regs
__device__ __forceinline__ void gemm_x3(unsigned sbase, unsigned aH, unsigned aL,
                                        unsigned bH, unsigned bL,
                                        int m0, int n0, int lane,
                                        float acc[4][4]) {
    int aRow = lane & 15;
    int aKoff = (lane >> 4) * 16;
    int bRow = (lane & 7) + (lane >> 4) * 8;     // lanes 16-31 -> second n8 group
    int bKoff = ((lane >> 3) & 1) * 16;          // k half
#pragma unroll 1
    for (int ks = 0; ks < 8; ks++) {
        int kb = ks * 32;
        unsigned ah[4], al[4];
        ldsm4(ah, sbase + aH + swb(m0 + aRow, kb + aKoff));
        ldsm4(al, sbase + aL + swb(m0 + aRow, kb + aKoff));
#pragma unroll
        for (int np = 0; np < 2; np++) {
            unsigned bh[4], bl[4];
            ldsm4(bh, sbase + bH + swb(n0 + np * 16 + bRow, kb + bKoff));
            ldsm4(bl, sbase + bL + swb(n0 + np * 16 + bRow, kb + bKoff));
            mma16816(acc[np * 2], ah, bh);
            mma16816(acc[np * 2], al, bh);
            mma16816(acc[np * 2], ah, bl);
            mma16816(acc[np * 2 + 1], ah, bh + 2);
            mma16816(acc[np * 2 + 1], al, bh + 2);
            mma16816(acc[np * 2 + 1], ah, bl + 2);
        }
    }
}

__global__ void __launch_bounds__(NTHR, 1) k_layer(
    const float* __restrict__ h_in, float* __restrict__ h_out,
    const float* __restrict__ W1, const float* __restrict__ B1,
    const float* __restrict__ W2, const float* __restrict__ B2,
    int layer)
{
    extern __shared__ char smraw[];
    char* sm = (char*)(((unsigned long long)smraw + 1023ull) & ~1023ull);
    unsigned sbase = smem_u32(sm);
    __shared__ int s_tile;
    int tid = threadIdx.x, lane = tid & 31, wid = tid >> 5;
    int par = layer & 1;

    // stage W^T hi/lo (swizzled) + biases
    for (int idx = tid; idx < DD * DD; idx += NTHR) {
        int k = idx >> 7, n = idx & 127;
        float v1 = W1[idx], v2 = W2[idx];
        unsigned o = swb(n, 2 * k);
        __nv_bfloat16 h1 = __float2bfloat16(v1), h2 = __float2bfloat16(v2);
        *(__nv_bfloat16*)(sm + SM_B1H + o) = h1;
        *(__nv_bfloat16*)(sm + SM_B1L + o) = __float2bfloat16(v1 - __bfloat162float(h1));
        *(__nv_bfloat16*)(sm + SM_B2H + o) = h2;
        *(__nv_bfloat16*)(sm + SM_B2L + o) = __float2bfloat16(v2 - __bfloat162float(h2));
    }
    if (tid < 128) {
        ((float*)(sm + SM_BI1))[tid] = B1[tid];
        ((float*)(sm + SM_BI2))[tid] = B2[tid];
    }
    __syncthreads();

    const float4* hin4 = (const float4*)h_in;
    const float* bi1 = (const float*)(sm + SM_BI1);
    const float* bi2 = (const float*)(sm + SM_BI2);

    int warpM = wid & 7, warpN = wid >> 3;       // 8 x 4 warp grid
    int m0 = warpM * 16, n0 = warpN * 32;
    int r0 = lane >> 2, cq = (lane & 3) * 2;

    for (;;) {
        if (tid == 0) s_tile = atomicAdd(&g_tilectr[layer], 1);
        __syncthreads();
        int tile = s_tile;
        if (tile >= NUM_TILES) break;

        // ---- gather: 4 nodes/warp, 4 float4 loads in flight ----
#pragma unroll 1
        for (int mi = 0; mi < 4; mi++) {
            int m = wid * 4 + mi;
            int n = tile * TM + m;
            float4 t = make_float4(0.f, 0.f, 0.f, 0.f);
            if (n < NN) {
                float4 a0 = t, a1 = t, a2 = t, a3 = t;
                int beg = g_rowptr[n], end = g_rowptr[n + 1];
                int e = beg;
                for (; e + 4 <= end; e += 4) {
                    int s0 = g_colsrc[e],     s1 = g_colsrc[e + 1];
                    int s2 = g_colsrc[e + 2], s3 = g_colsrc[e + 3];
                    a0 = f4add(a0, __ldg(&hin4[s0 * 32 + lane]));
                    a1 = f4add(a1, __ldg(&hin4[s1 * 32 + lane]));
                    a2 = f4add(a2, __ldg(&hin4[s2 * 32 + lane]));
                    a3 = f4add(a3, __ldg(&hin4[s3 * 32 + lane]));
                }
                for (; e < end; e++)
                    a0 = f4add(a0, __ldg(&hin4[g_colsrc[e] * 32 + lane]));
                t = f4add(f4add(__ldg(&hin4[n * 32 + lane]), a0),
                          f4add(a1, f4add(a2, a3)));
            }
            __nv_bfloat16 hx = __float2bfloat16(t.x), hy = __float2bfloat16(t.y);
            __nv_bfloat16 hz = __float2bfloat16(t.z), hw = __float2bfloat16(t.w);
            unsigned hp0 = pack_bf2(t.x, t.y), hp1 = pack_bf2(t.z, t.w);
            unsigned lp0 = pack_bf2(t.x - __bfloat162float(hx), t.y - __bfloat162float(hy));
            unsigned lp1 = pack_bf2(t.z - __bfloat162float(hz), t.w - __bfloat162float(hw));
            unsigned so = swb(m, lane * 8);
            *(uint2*)(sm + SM_A0 + so) = make_uint2(hp0, hp1);
            *(uint2*)(sm + SM_A1 + so) = make_uint2(lp0, lp1);
        }
        __syncthreads();

        // ---- MLP1 ----
        float acc[4][4];
#pragma unroll
        for (int b = 0; b < 4; b++)
#pragma unroll
            for (int c = 0; c < 4; c++) acc[b][c] = 0.f;
        gemm_x3(sbase, SM_A0, SM_A1, SM_B1H, SM_B1L, m0, n0, lane, acc);
        __syncthreads();

        // ---- epilogue 1: bias+relu, re-split into A ----
#pragma unroll
        for (int nt = 0; nt < 4; nt++) {
            int c = n0 + nt * 8 + cq;
            float bb0 = bi1[c], bb1 = bi1[c + 1];
            int mA = m0 + r0;
            float v0 = fmaxf(acc[nt][0] + bb0, 0.f);
            float v1 = fmaxf(acc[nt][1] + bb1, 0.f);
            float v2 = fmaxf(acc[nt][2] + bb0, 0.f);
            float v3 = fmaxf(acc[nt][3] + bb1, 0.f);
            __nv_bfloat16 h0 = __float2bfloat16(v0), h1 = __float2bfloat16(v1);
            __nv_bfloat16 h2 = __float2bfloat16(v2), h3 = __float2bfloat16(v3);
            unsigned oA = swb(mA, 2 * c), oB = swb(mA + 8, 2 * c);
            *(unsigned*)(sm + SM_A0 + oA) = pack_bf2(v0, v1);
            *(unsigned*)(sm + SM_A1 + oA) =
                pack_bf2(v0 - __bfloat162float(h0), v1 - __bfloat162float(h1));
            *(unsigned*)(sm + SM_A0 + oB) = pack_bf2(v2, v3);
            *(unsigned*)(sm + SM_A1 + oB) =
                pack_bf2(v2 - __bfloat162float(h2), v3 - __bfloat162float(h3));
        }
        __syncthreads();

        // ---- MLP2 ----
#pragma unroll
        for (int b = 0; b < 4; b++)
#pragma unroll
            for (int c = 0; c < 4; c++) acc[b][c] = 0.f;
        gemm_x3(sbase, SM_A0, SM_A1, SM_B2H, SM_B2L, m0, n0, lane, acc);
        __syncthreads();   // A reads done before stats scratch / next gather

        // ---- epilogue 2: bias+relu -> gmem; keep in acc for stats ----
        {
            int mA = m0 + r0;
            int nd0 = tile * TM + mA, nd1 = nd0 + 8;
#pragma unroll
            for (int nt = 0; nt < 4; nt++) {
                int c = n0 + nt * 8 + cq;
                float bb0 = bi2[c], bb1 = bi2[c + 1];
                float o0 = fmaxf(acc[nt][0] + bb0, 0.f);
                float o1 = fmaxf(acc[nt][1] + bb1, 0.f);
                float o2 = fmaxf(acc[nt][2] + bb0, 0.f);
                float o3 = fmaxf(acc[nt][3] + bb1, 0.f);
                acc[nt][0] = o0; acc[nt][1] = o1;
                acc[nt][2] = o2; acc[nt][3] = o3;
                if (nd0 < NN) *(float2*)(h_out + (size_t)nd0 * DD + c) = make_float2(o0, o1);
                if (nd1 < NN) *(float2*)(h_out + (size_t)nd1 * DD + c) = make_float2(o2, o3);
            }
        }

        // ---- fused GraphNorm stats ----
        {
            int base = tile * TM;
            int gs = g_nodeg[base];
            int lastn = base + TM - 1; if (lastn >= NN) lastn = NN - 1;
            int ge = g_nodeg[lastn];
            int nd0 = base + m0 + r0, nd1 = nd0 + 8;
            int rb0 = (nd0 < NN) ? g_nodeg[nd0] : -1;
            int rb1 = (nd1 < NN) ? g_nodeg[nd1] : -1;
            float* scrS = (float*)(sm + SM_A0);   // [8 warpM][128] floats = 4KB
            float* scrQ = scrS + 1024;            // 4KB
            for (int g = gs; g <= ge; g++) {
#pragma unroll
                for (int nt = 0; nt < 4; nt++) {
                    float p0 = 0.f, p1 = 0.f, q0 = 0.f, q1 = 0.f;
                    if (rb0 == g) {
                        float v0 = acc[nt][0], v1 = acc[nt][1];
                        p0 += v0; q0 += v0 * v0; p1 += v1; q1 += v1 * v1;
                    }
                    if (rb1 == g) {
                        float v0 = acc[nt][2], v1 = acc[nt][3];
                        p0 += v0; q0 += v0 * v0; p1 += v1; q1 += v1 * v1;
                    }
#pragma unroll
                    for (int o = 4; o <= 16; o <<= 1) {
                        p0 += __shfl_xor_sync(0xffffffffu, p0, o);
                        p1 += __shfl_xor_sync(0xffffffffu, p1, o);
                        q0 += __shfl_xor_sync(0xffffffffu, q0, o);
                        q1 += __shfl_xor_sync(0xffffffffu, q1, o);
                    }
                    if (r0 == 0) {   // lanes 0-3
                        int c = n0 + nt * 8 + cq;
                        scrS[warpM * 128 + c]     = p0;
                        scrS[warpM * 128 + c + 1] = p1;
                        scrQ[warpM * 128 + c]     = q0;
                        scrQ[warpM * 128 + c + 1] = q1;
                    }
                }
                __syncthreads();
                if (tid < 128) {
                    float s = 0.f;
#pragma unroll
                    for (int j = 0; j < 8; j++) s += scrS[j * 128 + tid];
                    atomicAdd(&g_sum2[par][g * DD + tid], s);
                } else if (tid < 256) {
                    int d2 = tid - 128;
                    float s = 0.f;
#pragma unroll
                    for (int j = 0; j < 8; j++) s += scrQ[j * 128 + d2];
                    atomicAdd(&g_sumsq2[par][g * DD + d2], s);
                }
                __syncthreads();
            }
        }
    }
}

// ---------------- GraphNorm normalize (+zero next-parity stats, +readout) ----------------
__global__ void k_gnorm2(float* __restrict__ h, const float* __restrict__ w,
                         const float* __restrict__ b, const float* __restrict__ ms,
                         int layer) {
    int par = layer & 1;
    int g = blockIdx.x, c = blockIdx.y, d = threadIdx.x;
    int s = g_gstart[g], n = g_gstart[g + 1] - s;
    int is = s + (n * c) / 8, ie = s + (n * (c + 1)) / 8;
    float cnt = g_countsf[g];
    float m0 = g_sum2[par][g * DD + d] / cnt;
    float a = m0 * ms[d];
    float var = g_sumsq2[par][g * DD + d] / cnt - 2.f * a * m0 + a * a;
    float inv = rsqrtf(var + 1e-5f) * w[d];
    float bb = b[d];
    g_sum2[par ^ 1][g * DD + d] = 0.f;
    g_sumsq2[par ^ 1][g * DD + d] = 0.f;
    float local = 0.f;
    for (int i = is; i < ie; i++) {
        float o = fmaxf((h[(size_t)i * DD + d] - a) * inv + bb, 0.f);
        h[(size_t)i * DD + d] = o;
        local += o;
    }
    if (layer == NL - 1 && ie > is) atomicAdd(&g_gsum[g * DD + d], local);
}

// ---------------- head MLP + log_softmax ----------------
__global__ void k_final(const float* __restrict__ fw1, const float* __restrict__ fb1,
                        const float* __restrict__ fw2, const float* __restrict__ fb2,
                        const float* __restrict__ fw3, const float* __restrict__ fb3,
                        float* __restrict__ out) {
    __shared__ float s0[DD], s1[DD], slog[NC], lse;
    int g = blockIdx.x, d = threadIdx.x;
    s0[d] = g_gsum[g * DD + d];
    __syncthreads();
    float a = fb1[d];
#pragma unroll 4
    for (int k = 0; k < DD; k++) a += s0[k] * fw1[k * DD + d];
    s1[d] = fmaxf(a, 0.f);
    __syncthreads();
    float bv = fb2[d];
#pragma unroll 4
    for (int k = 0; k < DD; k++) bv += s1[k] * fw2[k * DD + d];
    s0[d] = fmaxf(bv, 0.f);
    __syncthreads();
    if (d < NC) {
        float c = fb3[d];
        for (int k = 0; k < DD; k++) c += s0[k] * fw3[k * NC + d];
        slog[d] = c;
    }
    __syncthreads();
    if (d == 0) {
        float mx = -1e30f;
        for (int c = 0; c < NC; c++) mx = fmaxf(mx, slog[c]);
        float se = 0.f;
        for (int c = 0; c < NC; c++) se += expf(slog[c] - mx);
        lse = mx + logf(se);
    }
    __syncthreads();
    if (d < NC) out[g * NC + d] = slog[d] - lse;
}

// ---------------- launch ----------------
extern "C" void kernel_launch(void* const* d_in, const int* in_sizes, int n_in,
                              void* d_out, int out_size) {
    const float* x   = (const float*)d_in[0];
    const float* gw1 = (const float*)d_in[1];
    const float* gb1 = (const float*)d_in[2];
    const float* gw2 = (const float*)d_in[3];
    const float* gb2 = (const float*)d_in[4];
    const float* gnw = (const float*)d_in[5];
    const float* gnb = (const float*)d_in[6];
    const float* gns = (const float*)d_in[7];
    const float* fw1 = (const float*)d_in[8];
    const float* fb1 = (const float*)d_in[9];
    const float* fw2 = (const float*)d_in[10];
    const float* fb2 = (const float*)d_in[11];
    const float* fw3 = (const float*)d_in[12];
    const float* fb3 = (const float*)d_in[13];
    const void*  ei  = d_in[14];
    const void*  bat = d_in[15];
    float* out = (float*)d_out;

    cudaFuncSetAttribute(k_layer, cudaFuncAttributeMaxDynamicSharedMemorySize, DYN_SMEM);
    int nsm = 148;
    cudaDeviceGetAttribute(&nsm, cudaDevAttrMultiProcessorCount, 0);

    void* p = nullptr;
    cudaGetSymbolAddress(&p, g_hbuf);
    float* hA = (float*)p;
    float* hB = hA + (size_t)NN * DD;

    k_pre<<<nsm, 256>>>(ei, bat);

    const float* cur = x;
    for (int l = 0; l < NL; l++) {
        float* ob = (l & 1) ? hB : hA;
        k_layer<<<nsm, NTHR, DYN_SMEM>>>(cur, ob,
                                         gw1 + l * DD * DD, gb1 + l * DD,
                                         gw2 + l * DD * DD, gb2 + l * DD, l);
        k_gnorm2<<<dim3(NG, 8), DD>>>(ob, gnw + l * DD, gnb + l * DD, gns + l * DD, l);
        cur = ob;
    }
    k_final<<<NG, DD>>>(fw1, fb1, fw2, fb2, fw3, fb3, out);
}

// round 13
// speedup vs baseline: 1.9348x; 1.0498x over previous
#include <cuda_runtime.h>
#include <cuda_bf16.h>

#define NN 50000
#define NE 800000
#define NG 128
#define DD 128
#define NL 4
#define NC 10
#define TM 64
#define NUM_TILES ((NN + TM - 1) / TM)   // 782
#define NTHR 1024

// ---------------- device scratch ----------------
__device__ float g_hbuf[2][NN * DD];
__device__ int   g_deg[NN];
__device__ int   g_rowptr[NN + 1];
__device__ int   g_cursor[NN];
__device__ int   g_colsrc[NE];
__device__ int   g_gstart[NG + 1];
__device__ int   g_nodeg[NN];
__device__ float g_countsf[NG];
__device__ float g_sum2[2][NG * DD];
__device__ float g_sumsq2[2][NG * DD];
__device__ float g_gsum[NG * DD];
__device__ int   g_tilectr[NL];
__device__ int   g_blocksum[256];
__device__ int   g_blockpre[256];
__device__ int   g_ei64, g_b64;
__device__ unsigned g_sync_count = 0;
__device__ volatile unsigned g_sync_gen = 0;

// ---------------- helpers ----------------
__device__ __forceinline__ unsigned smem_u32(const void* p) {
    unsigned a;
    asm("{ .reg .u64 t; cvta.to.shared.u64 t, %1; cvt.u32.u64 %0, t; }" : "=r"(a) : "l"(p));
    return a;
}
// swizzled byte offset inside a [rows x 256 bytes] bf16 tile
__device__ __forceinline__ unsigned swb(int r, int kb) {
    unsigned w = (unsigned)kb & 127u;
    unsigned sw = w ^ (((unsigned)r & 7u) << 4);
    return (unsigned)r * 256u + ((unsigned)kb & 128u) + sw;
}
__device__ __forceinline__ unsigned pack_bf2(float a, float b) {
    __nv_bfloat162 p = __floats2bfloat162_rn(a, b);
    return *reinterpret_cast<unsigned*>(&p);
}
__device__ __forceinline__ float4 f4add(float4 a, float4 b) {
    a.x += b.x; a.y += b.y; a.z += b.z; a.w += b.w; return a;
}
__device__ __forceinline__ void ldsm4(unsigned* r, unsigned addr) {
    asm volatile("ldmatrix.sync.aligned.m8n8.x4.shared.b16 {%0,%1,%2,%3}, [%4];"
        : "=r"(r[0]), "=r"(r[1]), "=r"(r[2]), "=r"(r[3]) : "r"(addr));
}
__device__ __forceinline__ void mma16816(float* d, const unsigned* a, const unsigned* b) {
    asm volatile("mma.sync.aligned.m16n8k16.row.col.f32.bf16.bf16.f32 "
        "{%0,%1,%2,%3}, {%4,%5,%6,%7}, {%8,%9}, {%0,%1,%2,%3};"
        : "+f"(d[0]), "+f"(d[1]), "+f"(d[2]), "+f"(d[3])
        : "r"(a[0]), "r"(a[1]), "r"(a[2]), "r"(a[3]), "r"(b[0]), "r"(b[1]));
}
// half-block barrier: named barrier 1 or 2, 512 threads
#define HBAR(h) asm volatile("bar.sync %0, 512;" :: "r"(1 + (h)) : "memory")

// ---------------- grid-wide barrier (all blocks resident) ----------------
__device__ __forceinline__ void gsync() {
    __syncthreads();
    if (threadIdx.x == 0) {
        unsigned gen = g_sync_gen;
        __threadfence();
        if (atomicAdd(&g_sync_count, 1u) == gridDim.x - 1) {
            g_sync_count = 0;
            __threadfence();
            g_sync_gen = gen + 1;
        } else {
            while (g_sync_gen == gen) { }
        }
        __threadfence();
    }
    __syncthreads();
}

// ---------------- fused persistent preprocessing ----------------
__global__ void __launch_bounds__(256) k_pre(const void* __restrict__ ei,
                                             const void* __restrict__ bat) {
    __shared__ int sscan[256];
    int tid = threadIdx.x, bid = blockIdx.x;
    int gtid = bid * 256 + tid, gsz = gridDim.x * 256;

    // phase 1: dtype detect + zero arrays
    if (bid == 0 && tid < 32) {
        const int* ei_w = (const int*)ei;
        const int* b_w = (const int*)bat;
        int ok1 = (ei_w[2 * tid + 1] == 0) && (ei_w[2 * (tid + 32) + 1] == 0);
        int a = __all_sync(0xffffffffu, ok1);
        int ok2 = (b_w[20001 + 2 * tid] == 0) && (b_w[20065 + 2 * tid] == 0);
        int b = __all_sync(0xffffffffu, ok2);
        if (tid == 0) { g_ei64 = a; g_b64 = b; }
    }
    for (int i = gtid; i < NN; i += gsz) g_deg[i] = 0;
    for (int i = gtid; i < NG * DD; i += gsz) {
        g_sum2[0][i] = 0.f; g_sum2[1][i] = 0.f;
        g_sumsq2[0][i] = 0.f; g_sumsq2[1][i] = 0.f;
        g_gsum[i] = 0.f;
    }
    if (gtid < NL) g_tilectr[gtid] = 0;
    gsync();

    // phase 2: graph bounds + degree histogram
    int e64 = g_ei64, b64 = g_b64;
    for (int i = gtid; i < NN; i += gsz) {
        int bi = b64 ? (int)((const long long*)bat)[i] : ((const int*)bat)[i];
        g_nodeg[i] = bi;
        int prev = -1;
        if (i > 0)
            prev = b64 ? (int)((const long long*)bat)[i - 1] : ((const int*)bat)[i - 1];
        for (int g = prev + 1; g <= bi; g++) g_gstart[g] = i;
        if (i == NN - 1)
            for (int g = bi + 1; g <= NG; g++) g_gstart[g] = NN;
    }
    for (int e = gtid; e < NE; e += gsz) {
        int d = e64 ? (int)((const long long*)ei)[NE + e] : ((const int*)ei)[NE + e];
        atomicAdd(&g_deg[d], 1);
    }
    gsync();

    // phase 3a: per-thread chunk sums + block scan
    const int CH = (NN + gsz - 1) / gsz;
    int base = gtid * CH;
    int s = 0;
    for (int j = 0; j < CH; j++) { int idx = base + j; if (idx < NN) s += g_deg[idx]; }
    sscan[tid] = s;
    __syncthreads();
    for (int off = 1; off < 256; off <<= 1) {
        int v = (tid >= off) ? sscan[tid - off] : 0;
        __syncthreads();
        sscan[tid] += v;
        __syncthreads();
    }
    int thr_excl = sscan[tid] - s;
    if (tid == 255) g_blocksum[bid] = sscan[255];
    gsync();

    // phase 3b: block 0 scans block totals (exclusive)
    if (bid == 0) {
        int v = (tid < (int)gridDim.x) ? g_blocksum[tid] : 0;
        sscan[tid] = v;
        __syncthreads();
        for (int off = 1; off < 256; off <<= 1) {
            int u = (tid >= off) ? sscan[tid - off] : 0;
            __syncthreads();
            sscan[tid] += u;
            __syncthreads();
        }
        if (tid < (int)gridDim.x) g_blockpre[tid] = sscan[tid] - v;
    }
    gsync();

    // phase 3c: write rowptr/cursor; counts
    int off = g_blockpre[bid] + thr_excl;
    for (int j = 0; j < CH; j++) {
        int idx = base + j;
        if (idx < NN) { g_rowptr[idx] = off; g_cursor[idx] = off; off += g_deg[idx]; }
    }
    if (gtid == 0) g_rowptr[NN] = NE;
    if (gtid < NG)
        g_countsf[gtid] = fmaxf((float)(g_gstart[gtid + 1] - g_gstart[gtid]), 1.f);
    gsync();

    // phase 4: fill CSR columns
    for (int e = gtid; e < NE; e += gsz) {
        int src, dst;
        if (e64) {
            src = (int)((const long long*)ei)[e];
            dst = (int)((const long long*)ei)[NE + e];
        } else {
            src = ((const int*)ei)[e];
            dst = ((const int*)ei)[NE + e];
        }
        g_colsrc[atomicAdd(&g_cursor[dst], 1)] = src;
    }
}

// ---------------- fused layer: two independent 512-thr halves, TM=64 each ----------------
#define SM_B1H 0
#define SM_B1L 32768
#define SM_B2H 65536
#define SM_B2L 98304
#define SM_BI1 131072
#define SM_BI2 131584
#define SM_AH0 132096
// half h: A0 at SM_AH0 + h*32768, A1 at +16384
#define DYN_SMEM (197632 + 1024)

// bf16x3 warp GEMM: 16 rows (m0, within 64-row A tile) x 32 cols (n0) x K=128
__device__ __forceinline__ void gemm_x3(unsigned sbase, unsigned aH, unsigned aL,
                                        unsigned bH, unsigned bL,
                                        int m0, int n0, int lane,
                                        float acc[4][4]) {
    int aRow = lane & 15;
    int aKoff = (lane >> 4) * 16;
    int bRow = (lane & 7) + (lane >> 4) * 8;
    int bKoff = ((lane >> 3) & 1) * 16;
#pragma unroll 1
    for (int ks = 0; ks < 8; ks++) {
        int kb = ks * 32;
        unsigned ah[4], al[4];
        ldsm4(ah, sbase + aH + swb(m0 + aRow, kb + aKoff));
        ldsm4(al, sbase + aL + swb(m0 + aRow, kb + aKoff));
#pragma unroll
        for (int np = 0; np < 2; np++) {
            unsigned bh[4], bl[4];
            ldsm4(bh, sbase + bH + swb(n0 + np * 16 + bRow, kb + bKoff));
            ldsm4(bl, sbase + bL + swb(n0 + np * 16 + bRow, kb + bKoff));
            mma16816(acc[np * 2], ah, bh);
            mma16816(acc[np * 2], al, bh);
            mma16816(acc[np * 2], ah, bl);
            mma16816(acc[np * 2 + 1], ah, bh + 2);
            mma16816(acc[np * 2 + 1], al, bh + 2);
            mma16816(acc[np * 2 + 1], ah, bl + 2);
        }
    }
}

__global__ void __launch_bounds__(NTHR, 1) k_layer(
    const float* __restrict__ h_in, float* __restrict__ h_out,
    const float* __restrict__ W1, const float* __restrict__ B1,
    const float* __restrict__ W2, const float* __restrict__ B2,
    int layer)
{
    extern __shared__ char smraw[];
    char* sm = (char*)(((unsigned long long)smraw + 1023ull) & ~1023ull);
    unsigned sbase = smem_u32(sm);
    __shared__ int s_tile[2];
    int tid = threadIdx.x, lane = tid & 31;
    int half = tid >> 9;                 // 0 or 1
    int htid = tid & 511;                // tid within half
    int hwid = htid >> 5;                // warp within half (0..15)
    int par = layer & 1;

    // stage W^T hi/lo (swizzled) + biases (whole block, once)
    for (int idx = tid; idx < DD * DD; idx += NTHR) {
        int k = idx >> 7, n = idx & 127;
        float v1 = W1[idx], v2 = W2[idx];
        unsigned o = swb(n, 2 * k);
        __nv_bfloat16 h1 = __float2bfloat16(v1), h2 = __float2bfloat16(v2);
        *(__nv_bfloat16*)(sm + SM_B1H + o) = h1;
        *(__nv_bfloat16*)(sm + SM_B1L + o) = __float2bfloat16(v1 - __bfloat162float(h1));
        *(__nv_bfloat16*)(sm + SM_B2H + o) = h2;
        *(__nv_bfloat16*)(sm + SM_B2L + o) = __float2bfloat16(v2 - __bfloat162float(h2));
    }
    if (tid < 128) {
        ((float*)(sm + SM_BI1))[tid] = B1[tid];
        ((float*)(sm + SM_BI2))[tid] = B2[tid];
    }
    __syncthreads();

    const float4* hin4 = (const float4*)h_in;
    const float* bi1 = (const float*)(sm + SM_BI1);
    const float* bi2 = (const float*)(sm + SM_BI2);

    unsigned aH = SM_AH0 + half * 32768u;
    unsigned aL = aH + 16384u;
    float* scrS = (float*)(sm + aH);          // stats scratch aliases own A0 (4KB)
    float* scrQ = scrS + 512;                 // next 2KB... [4][128] each

    int warpM = hwid & 3, warpN = hwid >> 2;  // 4 x 4 warp grid per half
    int m0 = warpM * 16, n0 = warpN * 32;
    int r0 = lane >> 2, cq = (lane & 3) * 2;

    for (;;) {
        if (htid == 0) s_tile[half] = atomicAdd(&g_tilectr[layer], 1);
        HBAR(half);
        int tile = s_tile[half];
        if (tile >= NUM_TILES) break;

        // ---- gather: 4 nodes/warp, 4 float4 loads in flight ----
#pragma unroll 1
        for (int mi = 0; mi < 4; mi++) {
            int m = hwid * 4 + mi;
            int n = tile * TM + m;
            float4 t = make_float4(0.f, 0.f, 0.f, 0.f);
            if (n < NN) {
                float4 a0 = t, a1 = t, a2 = t, a3 = t;
                int beg = g_rowptr[n], end = g_rowptr[n + 1];
                int e = beg;
                for (; e + 4 <= end; e += 4) {
                    int s0 = g_colsrc[e],     s1 = g_colsrc[e + 1];
                    int s2 = g_colsrc[e + 2], s3 = g_colsrc[e + 3];
                    a0 = f4add(a0, __ldg(&hin4[s0 * 32 + lane]));
                    a1 = f4add(a1, __ldg(&hin4[s1 * 32 + lane]));
                    a2 = f4add(a2, __ldg(&hin4[s2 * 32 + lane]));
                    a3 = f4add(a3, __ldg(&hin4[s3 * 32 + lane]));
                }
                for (; e < end; e++)
                    a0 = f4add(a0, __ldg(&hin4[g_colsrc[e] * 32 + lane]));
                t = f4add(f4add(__ldg(&hin4[n * 32 + lane]), a0),
                          f4add(a1, f4add(a2, a3)));
            }
            __nv_bfloat16 hx = __float2bfloat16(t.x), hy = __float2bfloat16(t.y);
            __nv_bfloat16 hz = __float2bfloat16(t.z), hw = __float2bfloat16(t.w);
            unsigned hp0 = pack_bf2(t.x, t.y), hp1 = pack_bf2(t.z, t.w);
            unsigned lp0 = pack_bf2(t.x - __bfloat162float(hx), t.y - __bfloat162float(hy));
            unsigned lp1 = pack_bf2(t.z - __bfloat162float(hz), t.w - __bfloat162float(hw));
            unsigned so = swb(m, lane * 8);
            *(uint2*)(sm + aH + so) = make_uint2(hp0, hp1);
            *(uint2*)(sm + aL + so) = make_uint2(lp0, lp1);
        }
        HBAR(half);

        // ---- MLP1 ----
        float acc[4][4];
#pragma unroll
        for (int b = 0; b < 4; b++)
#pragma unroll
            for (int c = 0; c < 4; c++) acc[b][c] = 0.f;
        gemm_x3(sbase, aH, aL, SM_B1H, SM_B1L, m0, n0, lane, acc);
        HBAR(half);

        // ---- epilogue 1: bias+relu, re-split into A ----
#pragma unroll
        for (int nt = 0; nt < 4; nt++) {
            int c = n0 + nt * 8 + cq;
            float bb0 = bi1[c], bb1 = bi1[c + 1];
            int mA = m0 + r0;
            float v0 = fmaxf(acc[nt][0] + bb0, 0.f);
            float v1 = fmaxf(acc[nt][1] + bb1, 0.f);
            float v2 = fmaxf(acc[nt][2] + bb0, 0.f);
            float v3 = fmaxf(acc[nt][3] + bb1, 0.f);
            __nv_bfloat16 h0 = __float2bfloat16(v0), h1 = __float2bfloat16(v1);
            __nv_bfloat16 h2 = __float2bfloat16(v2), h3 = __float2bfloat16(v3);
            unsigned oA = swb(mA, 2 * c), oB = swb(mA + 8, 2 * c);
            *(unsigned*)(sm + aH + oA) = pack_bf2(v0, v1);
            *(unsigned*)(sm + aL + oA) =
                pack_bf2(v0 - __bfloat162float(h0), v1 - __bfloat162float(h1));
            *(unsigned*)(sm + aH + oB) = pack_bf2(v2, v3);
            *(unsigned*)(sm + aL + oB) =
                pack_bf2(v2 - __bfloat162float(h2), v3 - __bfloat162float(h3));
        }
        HBAR(half);

        // ---- MLP2 ----
#pragma unroll
        for (int b = 0; b < 4; b++)
#pragma unroll
            for (int c = 0; c < 4; c++) acc[b][c] = 0.f;
        gemm_x3(sbase, aH, aL, SM_B2H, SM_B2L, m0, n0, lane, acc);
        HBAR(half);   // all A reads done before stats scratch overwrites A0

        // ---- epilogue 2: bias+relu -> gmem; keep in acc for stats ----
        {
            int mA = m0 + r0;
            int nd0 = tile * TM + mA, nd1 = nd0 + 8;
#pragma unroll
            for (int nt = 0; nt < 4; nt++) {
                int c = n0 + nt * 8 + cq;
                float bb0 = bi2[c], bb1 = bi2[c + 1];
                float o0 = fmaxf(acc[nt][0] + bb0, 0.f);
                float o1 = fmaxf(acc[nt][1] + bb1, 0.f);
                float o2 = fmaxf(acc[nt][2] + bb0, 0.f);
                float o3 = fmaxf(acc[nt][3] + bb1, 0.f);
                acc[nt][0] = o0; acc[nt][1] = o1;
                acc[nt][2] = o2; acc[nt][3] = o3;
                if (nd0 < NN) *(float2*)(h_out + (size_t)nd0 * DD + c) = make_float2(o0, o1);
                if (nd1 < NN) *(float2*)(h_out + (size_t)nd1 * DD + c) = make_float2(o2, o3);
            }
        }

        // ---- fused GraphNorm stats ----
        {
            int base = tile * TM;
            int gs = g_nodeg[base];
            int lastn = base + TM - 1; if (lastn >= NN) lastn = NN - 1;
            int ge = g_nodeg[lastn];
            int nd0 = base + m0 + r0, nd1 = nd0 + 8;
            int rb0 = (nd0 < NN) ? g_nodeg[nd0] : -1;
            int rb1 = (nd1 < NN) ? g_nodeg[nd1] : -1;
            for (int g = gs; g <= ge; g++) {
#pragma unroll
                for (int nt = 0; nt < 4; nt++) {
                    float p0 = 0.f, p1 = 0.f, q0 = 0.f, q1 = 0.f;
                    if (rb0 == g) {
                        float v0 = acc[nt][0], v1 = acc[nt][1];
                        p0 += v0; q0 += v0 * v0; p1 += v1; q1 += v1 * v1;
                    }
                    if (rb1 == g) {
                        float v0 = acc[nt][2], v1 = acc[nt][3];
                        p0 += v0; q0 += v0 * v0; p1 += v1; q1 += v1 * v1;
                    }
#pragma unroll
                    for (int o = 4; o <= 16; o <<= 1) {
                        p0 += __shfl_xor_sync(0xffffffffu, p0, o);
                        p1 += __shfl_xor_sync(0xffffffffu, p1, o);
                        q0 += __shfl_xor_sync(0xffffffffu, q0, o);
                        q1 += __shfl_xor_sync(0xffffffffu, q1, o);
                    }
                    if (r0 == 0) {   // lanes 0-3
                        int c = n0 + nt * 8 + cq;
                        scrS[warpM * 128 + c]     = p0;
                        scrS[warpM * 128 + c + 1] = p1;
                        scrQ[warpM * 128 + c]     = q0;
                        scrQ[warpM * 128 + c + 1] = q1;
                    }
                }
                HBAR(half);
                if (htid < 128) {
                    float s = scrS[htid] + scrS[128 + htid] + scrS[256 + htid] + scrS[384 + htid];
                    atomicAdd(&g_sum2[par][g * DD + htid], s);
                } else if (htid < 256) {
                    int d2 = htid - 128;
                    float s = scrQ[d2] + scrQ[128 + d2] + scrQ[256 + d2] + scrQ[384 + d2];
                    atomicAdd(&g_sumsq2[par][g * DD + d2], s);
                }
                HBAR(half);
            }
        }
    }
}

// ---------------- GraphNorm normalize (+zero next-parity stats, +readout) ----------------
__global__ void k_gnorm2(float* __restrict__ h, const float* __restrict__ w,
                         const float* __restrict__ b, const float* __restrict__ ms,
                         int layer) {
    int par = layer & 1;
    int g = blockIdx.x, c = blockIdx.y, d = threadIdx.x;
    int s = g_gstart[g], n = g_gstart[g + 1] - s;
    int is = s + (n * c) / 8, ie = s + (n * (c + 1)) / 8;
    float cnt = g_countsf[g];
    float m0 = g_sum2[par][g * DD + d] / cnt;
    float a = m0 * ms[d];
    float var = g_sumsq2[par][g * DD + d] / cnt - 2.f * a * m0 + a * a;
    float inv = rsqrtf(var + 1e-5f) * w[d];
    float bb = b[d];
    g_sum2[par ^ 1][g * DD + d] = 0.f;
    g_sumsq2[par ^ 1][g * DD + d] = 0.f;
    float local = 0.f;
    for (int i = is; i < ie; i++) {
        float o = fmaxf((h[(size_t)i * DD + d] - a) * inv + bb, 0.f);
        h[(size_t)i * DD + d] = o;
        local += o;
    }
    if (layer == NL - 1 && ie > is) atomicAdd(&g_gsum[g * DD + d], local);
}

// ---------------- head MLP + log_softmax ----------------
__global__ void k_final(const float* __restrict__ fw1, const float* __restrict__ fb1,
                        const float* __restrict__ fw2, const float* __restrict__ fb2,
                        const float* __restrict__ fw3, const float* __restrict__ fb3,
                        float* __restrict__ out) {
    __shared__ float s0[DD], s1[DD], slog[NC], lse;
    int g = blockIdx.x, d = threadIdx.x;
    s0[d] = g_gsum[g * DD + d];
    __syncthreads();
    float a = fb1[d];
#pragma unroll 4
    for (int k = 0; k < DD; k++) a += s0[k] * fw1[k * DD + d];
    s1[d] = fmaxf(a, 0.f);
    __syncthreads();
    float bv = fb2[d];
#pragma unroll 4
    for (int k = 0; k < DD; k++) bv += s1[k] * fw2[k * DD + d];
    s0[d] = fmaxf(bv, 0.f);
    __syncthreads();
    if (d < NC) {
        float c = fb3[d];
        for (int k = 0; k < DD; k++) c += s0[k] * fw3[k * NC + d];
        slog[d] = c;
    }
    __syncthreads();
    if (d == 0) {
        float mx = -1e30f;
        for (int c = 0; c < NC; c++) mx = fmaxf(mx, slog[c]);
        float se = 0.f;
        for (int c = 0; c < NC; c++) se += expf(slog[c] - mx);
        lse = mx + logf(se);
    }
    __syncthreads();
    if (d < NC) out[g * NC + d] = slog[d] - lse;
}

// ---------------- launch ----------------
extern "C" void kernel_launch(void* const* d_in, const int* in_sizes, int n_in,
                              void* d_out, int out_size) {
    const float* x   = (const float*)d_in[0];
    const float* gw1 = (const float*)d_in[1];
    const float* gb1 = (const float*)d_in[2];
    const float* gw2 = (const float*)d_in[3];
    const float* gb2 = (const float*)d_in[4];
    const float* gnw = (const float*)d_in[5];
    const float* gnb = (const float*)d_in[6];
    const float* gns = (const float*)d_in[7];
    const float* fw1 = (const float*)d_in[8];
    const float* fb1 = (const float*)d_in[9];
    const float* fw2 = (const float*)d_in[10];
    const float* fb2 = (const float*)d_in[11];
    const float* fw3 = (const float*)d_in[12];
    const float* fb3 = (const float*)d_in[13];
    const void*  ei  = d_in[14];
    const void*  bat = d_in[15];
    float* out = (float*)d_out;

    cudaFuncSetAttribute(k_layer, cudaFuncAttributeMaxDynamicSharedMemorySize, DYN_SMEM);
    int nsm = 148;
    cudaDeviceGetAttribute(&nsm, cudaDevAttrMultiProcessorCount, 0);

    void* p = nullptr;
    cudaGetSymbolAddress(&p, g_hbuf);
    float* hA = (float*)p;
    float* hB = hA + (size_t)NN * DD;

    k_pre<<<nsm, 256>>>(ei, bat);

    const float* cur = x;
    for (int l = 0; l < NL; l++) {
        float* ob = (l & 1) ? hB : hA;
        k_layer<<<nsm, NTHR, DYN_SMEM>>>(cur, ob,
                                         gw1 + l * DD * DD, gb1 + l * DD,
                                         gw2 + l * DD * DD, gb2 + l * DD, l);
        k_gnorm2<<<dim3(NG, 8), DD>>>(ob, gnw + l * DD, gnb + l * DD, gns + l * DD, l);
        cur = ob;
    }
    k_final<<<NG, DD>>>(fw1, fb1, fw2, fb2, fw3, fb3, out);
}

// round 14
// speedup vs baseline: 2.0652x; 1.0674x over previous
#include <cuda_runtime.h>
#include <cuda_bf16.h>

#define NN 50000
#define NE 800000
#define NG 128
#define DD 128
#define NL 4
#define NC 10
#define TM 16
#define NUM_TILES ((NN + TM - 1) / TM)   // 3125
#define NTHR 1024

// ---------------- device scratch ----------------
__device__ float g_hbuf[2][NN * DD];
__device__ int   g_deg[NN];
__device__ int   g_rowptr[NN + 1];
__device__ int   g_cursor[NN];
__device__ int   g_colsrc[NE];
__device__ int   g_gstart[NG + 1];
__device__ int   g_nodeg[NN];
__device__ float g_countsf[NG];
__device__ float g_sum2[2][NG * DD];
__device__ float g_sumsq2[2][NG * DD];
__device__ float g_gsum[NG * DD];
__device__ int   g_tilectr[NL];
__device__ int   g_blocksum[256];
__device__ int   g_blockpre[256];
__device__ int   g_ei64, g_b64;
__device__ unsigned g_sync_count = 0;
__device__ volatile unsigned g_sync_gen = 0;

// ---------------- helpers ----------------
__device__ __forceinline__ unsigned smem_u32(const void* p) {
    unsigned a;
    asm("{ .reg .u64 t; cvta.to.shared.u64 t, %1; cvt.u32.u64 %0, t; }" : "=r"(a) : "l"(p));
    return a;
}
// swizzled byte offset inside a [rows x 256 bytes] bf16 tile
__device__ __forceinline__ unsigned swb(int r, int kb) {
    unsigned w = (unsigned)kb & 127u;
    unsigned sw = w ^ (((unsigned)r & 7u) << 4);
    return (unsigned)r * 256u + ((unsigned)kb & 128u) + sw;
}
__device__ __forceinline__ unsigned pack_bf2(float a, float b) {
    __nv_bfloat162 p = __floats2bfloat162_rn(a, b);
    return *reinterpret_cast<unsigned*>(&p);
}
__device__ __forceinline__ float4 f4add(float4 a, float4 b) {
    a.x += b.x; a.y += b.y; a.z += b.z; a.w += b.w; return a;
}
__device__ __forceinline__ void ldsm4(unsigned* r, unsigned addr) {
    asm volatile("ldmatrix.sync.aligned.m8n8.x4.shared.b16 {%0,%1,%2,%3}, [%4];"
        : "=r"(r[0]), "=r"(r[1]), "=r"(r[2]), "=r"(r[3]) : "r"(addr));
}
__device__ __forceinline__ void mma16816(float* d, const unsigned* a, const unsigned* b) {
    asm volatile("mma.sync.aligned.m16n8k16.row.col.f32.bf16.bf16.f32 "
        "{%0,%1,%2,%3}, {%4,%5,%6,%7}, {%8,%9}, {%0,%1,%2,%3};"
        : "+f"(d[0]), "+f"(d[1]), "+f"(d[2]), "+f"(d[3])
        : "r"(a[0]), "r"(a[1]), "r"(a[2]), "r"(a[3]), "r"(b[0]), "r"(b[1]));
}
// group barrier: 4 warps (128 threads), named barrier 1+grp (grp 0..7)
#define GBAR(g) asm volatile("bar.sync %0, 128;" :: "r"(1 + (g)) : "memory")

// ---------------- grid-wide barrier (all blocks resident) ----------------
__device__ __forceinline__ void gsync() {
    __syncthreads();
    if (threadIdx.x == 0) {
        unsigned gen = g_sync_gen;
        __threadfence();
        if (atomicAdd(&g_sync_count, 1u) == gridDim.x - 1) {
            g_sync_count = 0;
            __threadfence();
            g_sync_gen = gen + 1;
        } else {
            while (g_sync_gen == gen) { }
        }
        __threadfence();
    }
    __syncthreads();
}

// ---------------- fused persistent preprocessing ----------------
__global__ void __launch_bounds__(256) k_pre(const void* __restrict__ ei,
                                             const void* __restrict__ bat) {
    __shared__ int sscan[256];
    int tid = threadIdx.x, bid = blockIdx.x;
    int gtid = bid * 256 + tid, gsz = gridDim.x * 256;

    // phase 1: dtype detect + zero arrays
    if (bid == 0 && tid < 32) {
        const int* ei_w = (const int*)ei;
        const int* b_w = (const int*)bat;
        int ok1 = (ei_w[2 * tid + 1] == 0) && (ei_w[2 * (tid + 32) + 1] == 0);
        int a = __all_sync(0xffffffffu, ok1);
        int ok2 = (b_w[20001 + 2 * tid] == 0) && (b_w[20065 + 2 * tid] == 0);
        int b = __all_sync(0xffffffffu, ok2);
        if (tid == 0) { g_ei64 = a; g_b64 = b; }
    }
    for (int i = gtid; i < NN; i += gsz) g_deg[i] = 0;
    for (int i = gtid; i < NG * DD; i += gsz) {
        g_sum2[0][i] = 0.f; g_sum2[1][i] = 0.f;
        g_sumsq2[0][i] = 0.f; g_sumsq2[1][i] = 0.f;
        g_gsum[i] = 0.f;
    }
    if (gtid < NL) g_tilectr[gtid] = 0;
    gsync();

    // phase 2: graph bounds + degree histogram
    int e64 = g_ei64, b64 = g_b64;
    for (int i = gtid; i < NN; i += gsz) {
        int bi = b64 ? (int)((const long long*)bat)[i] : ((const int*)bat)[i];
        g_nodeg[i] = bi;
        int prev = -1;
        if (i > 0)
            prev = b64 ? (int)((const long long*)bat)[i - 1] : ((const int*)bat)[i - 1];
        for (int g = prev + 1; g <= bi; g++) g_gstart[g] = i;
        if (i == NN - 1)
            for (int g = bi + 1; g <= NG; g++) g_gstart[g] = NN;
    }
    for (int e = gtid; e < NE; e += gsz) {
        int d = e64 ? (int)((const long long*)ei)[NE + e] : ((const int*)ei)[NE + e];
        atomicAdd(&g_deg[d], 1);
    }
    gsync();

    // phase 3a: per-thread chunk sums + block scan
    const int CH = (NN + gsz - 1) / gsz;
    int base = gtid * CH;
    int s = 0;
    for (int j = 0; j < CH; j++) { int idx = base + j; if (idx < NN) s += g_deg[idx]; }
    sscan[tid] = s;
    __syncthreads();
    for (int off = 1; off < 256; off <<= 1) {
        int v = (tid >= off) ? sscan[tid - off] : 0;
        __syncthreads();
        sscan[tid] += v;
        __syncthreads();
    }
    int thr_excl = sscan[tid] - s;
    if (tid == 255) g_blocksum[bid] = sscan[255];
    gsync();

    // phase 3b: block 0 scans block totals (exclusive)
    if (bid == 0) {
        int v = (tid < (int)gridDim.x) ? g_blocksum[tid] : 0;
        sscan[tid] = v;
        __syncthreads();
        for (int off = 1; off < 256; off <<= 1) {
            int u = (tid >= off) ? sscan[tid - off] : 0;
            __syncthreads();
            sscan[tid] += u;
            __syncthreads();
        }
        if (tid < (int)gridDim.x) g_blockpre[tid] = sscan[tid] - v;
    }
    gsync();

    // phase 3c: write rowptr/cursor; counts
    int off = g_blockpre[bid] + thr_excl;
    for (int j = 0; j < CH; j++) {
        int idx = base + j;
        if (idx < NN) { g_rowptr[idx] = off; g_cursor[idx] = off; off += g_deg[idx]; }
    }
    if (gtid == 0) g_rowptr[NN] = NE;
    if (gtid < NG)
        g_countsf[gtid] = fmaxf((float)(g_gstart[gtid + 1] - g_gstart[gtid]), 1.f);
    gsync();

    // phase 4: fill CSR columns
    for (int e = gtid; e < NE; e += gsz) {
        int src, dst;
        if (e64) {
            src = (int)((const long long*)ei)[e];
            dst = (int)((const long long*)ei)[NE + e];
        } else {
            src = ((const int*)ei)[e];
            dst = ((const int*)ei)[NE + e];
        }
        g_colsrc[atomicAdd(&g_cursor[dst], 1)] = src;
    }
}

// ---------------- fused layer: 8 independent 4-warp pipelines, TM=16 each ----------------
#define SM_B1H 0
#define SM_B1L 32768
#define SM_B2H 65536
#define SM_B2L 98304
#define SM_BI1 131072
#define SM_BI2 131584
#define SM_A0  132096
// group g: hi at SM_A0 + g*8192, lo at +4096
#define DYN_SMEM (197632 + 1024)

// bf16x3 warp GEMM: 16 rows x 32 cols (n0) x K=128, acc = 16 regs
__device__ __forceinline__ void gemm_x3(unsigned sbase, unsigned aH, unsigned aL,
                                        unsigned bH, unsigned bL,
                                        int n0, int lane,
                                        float acc[4][4]) {
    int aRow = lane & 15;
    int aKoff = (lane >> 4) * 16;
    int bRow = (lane & 7) + (lane >> 4) * 8;
    int bKoff = ((lane >> 3) & 1) * 16;
#pragma unroll 1
    for (int ks = 0; ks < 8; ks++) {
        int kb = ks * 32;
        unsigned ah[4], al[4];
        ldsm4(ah, sbase + aH + swb(aRow, kb + aKoff));
        ldsm4(al, sbase + aL + swb(aRow, kb + aKoff));
#pragma unroll
        for (int np = 0; np < 2; np++) {
            unsigned bh[4], bl[4];
            ldsm4(bh, sbase + bH + swb(n0 + np * 16 + bRow, kb + bKoff));
            ldsm4(bl, sbase + bL + swb(n0 + np * 16 + bRow, kb + bKoff));
            mma16816(acc[np * 2], ah, bh);
            mma16816(acc[np * 2], al, bh);
            mma16816(acc[np * 2], ah, bl);
            mma16816(acc[np * 2 + 1], ah, bh + 2);
            mma16816(acc[np * 2 + 1], al, bh + 2);
            mma16816(acc[np * 2 + 1], ah, bl + 2);
        }
    }
}

__global__ void __launch_bounds__(NTHR, 1) k_layer(
    const float* __restrict__ h_in, float* __restrict__ h_out,
    const float* __restrict__ W1, const float* __restrict__ B1,
    const float* __restrict__ W2, const float* __restrict__ B2,
    int layer)
{
    extern __shared__ char smraw[];
    char* sm = (char*)(((unsigned long long)smraw + 1023ull) & ~1023ull);
    unsigned sbase = smem_u32(sm);
    __shared__ int s_tile[8];
    int tid = threadIdx.x, lane = tid & 31, wid = tid >> 5;
    int grp = wid >> 2;                  // 0..7
    int wlocal = wid & 3;                // warp within group
    int par = layer & 1;

    // stage W^T hi/lo (swizzled) + biases (whole block, once)
    for (int idx = tid; idx < DD * DD; idx += NTHR) {
        int k = idx >> 7, n = idx & 127;
        float v1 = W1[idx], v2 = W2[idx];
        unsigned o = swb(n, 2 * k);
        __nv_bfloat16 h1 = __float2bfloat16(v1), h2 = __float2bfloat16(v2);
        *(__nv_bfloat16*)(sm + SM_B1H + o) = h1;
        *(__nv_bfloat16*)(sm + SM_B1L + o) = __float2bfloat16(v1 - __bfloat162float(h1));
        *(__nv_bfloat16*)(sm + SM_B2H + o) = h2;
        *(__nv_bfloat16*)(sm + SM_B2L + o) = __float2bfloat16(v2 - __bfloat162float(h2));
    }
    if (tid < 128) {
        ((float*)(sm + SM_BI1))[tid] = B1[tid];
        ((float*)(sm + SM_BI2))[tid] = B2[tid];
    }
    __syncthreads();

    const float4* hin4 = (const float4*)h_in;
    const float* bi1 = (const float*)(sm + SM_BI1);
    const float* bi2 = (const float*)(sm + SM_BI2);

    unsigned aH = SM_A0 + grp * 8192u;
    unsigned aL = aH + 4096u;

    int n0 = wlocal * 32;
    int r0 = lane >> 2, cq = (lane & 3) * 2;

    for (;;) {
        if (wlocal == 0 && lane == 0)
            s_tile[grp] = atomicAdd(&g_tilectr[layer], 1);
        GBAR(grp);                       // also protects A against next gather WAR
        int tile = s_tile[grp];
        if (tile >= NUM_TILES) break;

        // ---- gather: 4 nodes/warp, 4 float4 loads in flight ----
#pragma unroll 1
        for (int mi = 0; mi < 4; mi++) {
            int m = wlocal * 4 + mi;
            int n = tile * TM + m;
            float4 t = make_float4(0.f, 0.f, 0.f, 0.f);
            if (n < NN) {
                float4 a0 = t, a1 = t, a2 = t, a3 = t;
                int beg = g_rowptr[n], end = g_rowptr[n + 1];
                int e = beg;
                for (; e + 4 <= end; e += 4) {
                    int s0 = g_colsrc[e],     s1 = g_colsrc[e + 1];
                    int s2 = g_colsrc[e + 2], s3 = g_colsrc[e + 3];
                    a0 = f4add(a0, __ldg(&hin4[s0 * 32 + lane]));
                    a1 = f4add(a1, __ldg(&hin4[s1 * 32 + lane]));
                    a2 = f4add(a2, __ldg(&hin4[s2 * 32 + lane]));
                    a3 = f4add(a3, __ldg(&hin4[s3 * 32 + lane]));
                }
                for (; e < end; e++)
                    a0 = f4add(a0, __ldg(&hin4[g_colsrc[e] * 32 + lane]));
                t = f4add(f4add(__ldg(&hin4[n * 32 + lane]), a0),
                          f4add(a1, f4add(a2, a3)));
            }
            __nv_bfloat16 hx = __float2bfloat16(t.x), hy = __float2bfloat16(t.y);
            __nv_bfloat16 hz = __float2bfloat16(t.z), hw = __float2bfloat16(t.w);
            unsigned hp0 = pack_bf2(t.x, t.y), hp1 = pack_bf2(t.z, t.w);
            unsigned lp0 = pack_bf2(t.x - __bfloat162float(hx), t.y - __bfloat162float(hy));
            unsigned lp1 = pack_bf2(t.z - __bfloat162float(hz), t.w - __bfloat162float(hw));
            unsigned so = swb(m, lane * 8);
            *(uint2*)(sm + aH + so) = make_uint2(hp0, hp1);
            *(uint2*)(sm + aL + so) = make_uint2(lp0, lp1);
        }
        GBAR(grp);

        // ---- MLP1 ----
        float acc[4][4];
#pragma unroll
        for (int b = 0; b < 4; b++)
#pragma unroll
            for (int c = 0; c < 4; c++) acc[b][c] = 0.f;
        gemm_x3(sbase, aH, aL, SM_B1H, SM_B1L, n0, lane, acc);
        GBAR(grp);

        // ---- epilogue 1: bias+relu, re-split into A ----
#pragma unroll
        for (int nt = 0; nt < 4; nt++) {
            int c = n0 + nt * 8 + cq;
            float bb0 = bi1[c], bb1 = bi1[c + 1];
            float v0 = fmaxf(acc[nt][0] + bb0, 0.f);
            float v1 = fmaxf(acc[nt][1] + bb1, 0.f);
            float v2 = fmaxf(acc[nt][2] + bb0, 0.f);
            float v3 = fmaxf(acc[nt][3] + bb1, 0.f);
            __nv_bfloat16 h0 = __float2bfloat16(v0), h1 = __float2bfloat16(v1);
            __nv_bfloat16 h2 = __float2bfloat16(v2), h3 = __float2bfloat16(v3);
            unsigned oA = swb(r0, 2 * c), oB = swb(r0 + 8, 2 * c);
            *(unsigned*)(sm + aH + oA) = pack_bf2(v0, v1);
            *(unsigned*)(sm + aL + oA) =
                pack_bf2(v0 - __bfloat162float(h0), v1 - __bfloat162float(h1));
            *(unsigned*)(sm + aH + oB) = pack_bf2(v2, v3);
            *(unsigned*)(sm + aL + oB) =
                pack_bf2(v2 - __bfloat162float(h2), v3 - __bfloat162float(h3));
        }
        GBAR(grp);

        // ---- MLP2 ----
#pragma unroll
        for (int b = 0; b < 4; b++)
#pragma unroll
            for (int c = 0; c < 4; c++) acc[b][c] = 0.f;
        gemm_x3(sbase, aH, aL, SM_B2H, SM_B2L, n0, lane, acc);

        // ---- epilogue 2: bias+relu -> gmem; keep in acc for stats (regs only) ----
        int nd0 = tile * TM + r0, nd1 = nd0 + 8;
#pragma unroll
        for (int nt = 0; nt < 4; nt++) {
            int c = n0 + nt * 8 + cq;
            float bb0 = bi2[c], bb1 = bi2[c + 1];
            float o0 = fmaxf(acc[nt][0] + bb0, 0.f);
            float o1 = fmaxf(acc[nt][1] + bb1, 0.f);
            float o2 = fmaxf(acc[nt][2] + bb0, 0.f);
            float o3 = fmaxf(acc[nt][3] + bb1, 0.f);
            acc[nt][0] = o0; acc[nt][1] = o1;
            acc[nt][2] = o2; acc[nt][3] = o3;
            if (nd0 < NN) *(float2*)(h_out + (size_t)nd0 * DD + c) = make_float2(o0, o1);
            if (nd1 < NN) *(float2*)(h_out + (size_t)nd1 * DD + c) = make_float2(o2, o3);
        }

        // ---- fused GraphNorm stats: shfl reduce + direct atomics (no barriers) ----
        {
            int base = tile * TM;
            int gs = g_nodeg[base];
            int lastn = base + TM - 1; if (lastn >= NN) lastn = NN - 1;
            int ge = g_nodeg[lastn];
            int rb0 = (nd0 < NN) ? g_nodeg[nd0] : -1;
            int rb1 = (nd1 < NN) ? g_nodeg[nd1] : -1;
            for (int g = gs; g <= ge; g++) {
#pragma unroll
                for (int nt = 0; nt < 4; nt++) {
                    float p0 = 0.f, p1 = 0.f, q0 = 0.f, q1 = 0.f;
                    if (rb0 == g) {
                        float v0 = acc[nt][0], v1 = acc[nt][1];
                        p0 += v0; q0 += v0 * v0; p1 += v1; q1 += v1 * v1;
                    }
                    if (rb1 == g) {
                        float v0 = acc[nt][2], v1 = acc[nt][3];
                        p0 += v0; q0 += v0 * v0; p1 += v1; q1 += v1 * v1;
                    }
#pragma unroll
                    for (int o = 4; o <= 16; o <<= 1) {
                        p0 += __shfl_xor_sync(0xffffffffu, p0, o);
                        p1 += __shfl_xor_sync(0xffffffffu, p1, o);
                        q0 += __shfl_xor_sync(0xffffffffu, q0, o);
                        q1 += __shfl_xor_sync(0xffffffffu, q1, o);
                    }
                    int c = n0 + nt * 8 + cq;
                    if (r0 == 0) {
                        atomicAdd(&g_sum2[par][g * DD + c],     p0);
                        atomicAdd(&g_sum2[par][g * DD + c + 1], p1);
                    } else if (r0 == 1) {
                        atomicAdd(&g_sumsq2[par][g * DD + c],     q0);
                        atomicAdd(&g_sumsq2[par][g * DD + c + 1], q1);
                    }
                }
            }
        }
    }
}

// ---------------- GraphNorm normalize (+zero next-parity stats, +readout) ----------------
__global__ void k_gnorm2(float* __restrict__ h, const float* __restrict__ w,
                         const float* __restrict__ b, const float* __restrict__ ms,
                         int layer) {
    int par = layer & 1;
    int g = blockIdx.x, c = blockIdx.y, d = threadIdx.x;
    int s = g_gstart[g], n = g_gstart[g + 1] - s;
    int is = s + (n * c) / 8, ie = s + (n * (c + 1)) / 8;
    float cnt = g_countsf[g];
    float m0 = g_sum2[par][g * DD + d] / cnt;
    float a = m0 * ms[d];
    float var = g_sumsq2[par][g * DD + d] / cnt - 2.f * a * m0 + a * a;
    float inv = rsqrtf(var + 1e-5f) * w[d];
    float bb = b[d];
    g_sum2[par ^ 1][g * DD + d] = 0.f;
    g_sumsq2[par ^ 1][g * DD + d] = 0.f;
    float local = 0.f;
    for (int i = is; i < ie; i++) {
        float o = fmaxf((h[(size_t)i * DD + d] - a) * inv + bb, 0.f);
        h[(size_t)i * DD + d] = o;
        local += o;
    }
    if (layer == NL - 1 && ie > is) atomicAdd(&g_gsum[g * DD + d], local);
}

// ---------------- head MLP + log_softmax ----------------
__global__ void k_final(const float* __restrict__ fw1, const float* __restrict__ fb1,
                        const float* __restrict__ fw2, const float* __restrict__ fb2,
                        const float* __restrict__ fw3, const float* __restrict__ fb3,
                        float* __restrict__ out) {
    __shared__ float s0[DD], s1[DD], slog[NC], lse;
    int g = blockIdx.x, d = threadIdx.x;
    s0[d] = g_gsum[g * DD + d];
    __syncthreads();
    float a = fb1[d];
#pragma unroll 4
    for (int k = 0; k < DD; k++) a += s0[k] * fw1[k * DD + d];
    s1[d] = fmaxf(a, 0.f);
    __syncthreads();
    float bv = fb2[d];
#pragma unroll 4
    for (int k = 0; k < DD; k++) bv += s1[k] * fw2[k * DD + d];
    s0[d] = fmaxf(bv, 0.f);
    __syncthreads();
    if (d < NC) {
        float c = fb3[d];
        for (int k = 0; k < DD; k++) c += s0[k] * fw3[k * NC + d];
        slog[d] = c;
    }
    __syncthreads();
    if (d == 0) {
        float mx = -1e30f;
        for (int c = 0; c < NC; c++) mx = fmaxf(mx, slog[c]);
        float se = 0.f;
        for (int c = 0; c < NC; c++) se += expf(slog[c] - mx);
        lse = mx + logf(se);
    }
    __syncthreads();
    if (d < NC) out[g * NC + d] = slog[d] - lse;
}

// ---------------- launch ----------------
extern "C" void kernel_launch(void* const* d_in, const int* in_sizes, int n_in,
                              void* d_out, int out_size) {
    const float* x   = (const float*)d_in[0];
    const float* gw1 = (const float*)d_in[1];
    const float* gb1 = (const float*)d_in[2];
    const float* gw2 = (const float*)d_in[3];
    const float* gb2 = (const float*)d_in[4];
    const float* gnw = (const float*)d_in[5];
    const float* gnb = (const float*)d_in[6];
    const float* gns = (const float*)d_in[7];
    const float* fw1 = (const float*)d_in[8];
    const float* fb1 = (const float*)d_in[9];
    const float* fw2 = (const float*)d_in[10];
    const float* fb2 = (const float*)d_in[11];
    const float* fw3 = (const float*)d_in[12];
    const float* fb3 = (const float*)d_in[13];
    const void*  ei  = d_in[14];
    const void*  bat = d_in[15];
    float* out = (float*)d_out;

    cudaFuncSetAttribute(k_layer, cudaFuncAttributeMaxDynamicSharedMemorySize, DYN_SMEM);
    int nsm = 148;
    cudaDeviceGetAttribute(&nsm, cudaDevAttrMultiProcessorCount, 0);

    void* p = nullptr;
    cudaGetSymbolAddress(&p, g_hbuf);
    float* hA = (float*)p;
    float* hB = hA + (size_t)NN * DD;

    k_pre<<<nsm, 256>>>(ei, bat);

    const float* cur = x;
    for (int l = 0; l < NL; l++) {
        float* ob = (l & 1) ? hB : hA;
        k_layer<<<nsm, NTHR, DYN_SMEM>>>(cur, ob,
                                         gw1 + l * DD * DD, gb1 + l * DD,
                                         gw2 + l * DD * DD, gb2 + l * DD, l);
        k_gnorm2<<<dim3(NG, 8), DD>>>(ob, gnw + l * DD, gnb + l * DD, gns + l * DD, l);
        cur = ob;
    }
    k_final<<<NG, DD>>>(fw1, fb1, fw2, fb2, fw3, fb3, out);
}